// round 2
// baseline (speedup 1.0000x reference)
#include <cuda_runtime.h>
#include <cuda_bf16.h>

// Problem constants: B=4, D=1024, N=2048, K=1024, fp32.
#define BATCH 4
#define DDIM  1024
#define NSEQ  2048
#define KDIM  1024

// ---------------- scratch (device globals; no allocation allowed) ----------
__device__ float g_WQT[DDIM * KDIM];          // W_Q^T  (D,K)
__device__ float g_WKT[DDIM * KDIM];          // W_K^T  (D,K)
__device__ float g_MT [DDIM * DDIM];          // (W_O^T W_V)^T  (D,D)
__device__ float g_q  [BATCH * KDIM * NSEQ];  // (b,K,N)
__device__ float g_kk [BATCH * KDIM * NSEQ];  // (b,K,N)
__device__ float g_XT [BATCH * NSEQ * DDIM];  // (b,N,D)
__device__ float g_ctx[BATCH * DDIM * NSEQ];  // (b,D,N)
__device__ float g_LT [BATCH * NSEQ * NSEQ];  // logits^T, then A^T in-place

// ---------------- transpose: out[c][r] = in[r][c] ---------------------------
__global__ void transpose32(const float* __restrict__ in, float* __restrict__ out,
                            int rows, int cols, long long sIn, long long sOut) {
    __shared__ float tile[32][33];
    const float* I = in  + (long long)blockIdx.z * sIn;
    float*       O = out + (long long)blockIdx.z * sOut;
    int r0 = blockIdx.y * 32, c0 = blockIdx.x * 32;
    int x = threadIdx.x, y = threadIdx.y;
#pragma unroll
    for (int j = y; j < 32; j += 8)
        tile[j][x] = I[(long long)(r0 + j) * cols + c0 + x];
    __syncthreads();
#pragma unroll
    for (int j = y; j < 32; j += 8)
        O[(long long)(c0 + j) * rows + r0 + x] = tile[x][j];
}

// ---------------- TN SGEMM: C[m][n] = sum_k A[k][m] * B[k][n] ---------------
// A: (Kk x M) row-major (ld=M). B: (Kk x Nn) row-major (ld=Nn). C: (M x Nn).
// Optional residual add (same layout as C). causal: skip tiles with m0 > n0+127
// (only the upper triangle incl. diagonal of C is needed for LT).
#define BM 128
#define BN 128
#define BK 8

__global__ __launch_bounds__(256, 2)
void tn_gemm(const float* __restrict__ A, const float* __restrict__ B,
             float* __restrict__ C, const float* __restrict__ Res,
             int M, int Nn, int Kk,
             long long sA, long long sB, long long sC, long long sRes,
             int causal) {
    int m0 = blockIdx.y * BM;
    int n0 = blockIdx.x * BN;
    if (causal && m0 > n0 + BN - 1) return;

    const float* Ab = A + (long long)blockIdx.z * sA;
    const float* Bb = B + (long long)blockIdx.z * sB;
    float*       Cb = C + (long long)blockIdx.z * sC;

    __shared__ float As[2][BK][BM];
    __shared__ float Bs[2][BK][BN];

    int tid = threadIdx.x;
    int lr = tid >> 5;          // k-row 0..7
    int lc = (tid & 31) << 2;   // col*4

    const float* Aptr = Ab + (long long)lr * M  + m0 + lc;
    const float* Bptr = Bb + (long long)lr * Nn + n0 + lc;

    float4 a4 = *(const float4*)Aptr;
    float4 b4 = *(const float4*)Bptr;
    *(float4*)&As[0][lr][lc] = a4;
    *(float4*)&Bs[0][lr][lc] = b4;
    __syncthreads();

    int tx = tid & 15, ty = tid >> 4;
    float acc[8][8];
#pragma unroll
    for (int r = 0; r < 8; ++r)
#pragma unroll
        for (int c = 0; c < 8; ++c) acc[r][c] = 0.f;

    int nk = Kk / BK;
    int buf = 0;
    for (int kt = 0; kt < nk; ++kt) {
        if (kt + 1 < nk) {
            a4 = *(const float4*)(Aptr + (long long)(kt + 1) * BK * M);
            b4 = *(const float4*)(Bptr + (long long)(kt + 1) * BK * Nn);
        }
#pragma unroll
        for (int k = 0; k < BK; ++k) {
            float a_[8], b_[8];
            *reinterpret_cast<float4*>(a_)     = *reinterpret_cast<const float4*>(&As[buf][k][ty * 8]);
            *reinterpret_cast<float4*>(a_ + 4) = *reinterpret_cast<const float4*>(&As[buf][k][ty * 8 + 4]);
            *reinterpret_cast<float4*>(b_)     = *reinterpret_cast<const float4*>(&Bs[buf][k][tx * 8]);
            *reinterpret_cast<float4*>(b_ + 4) = *reinterpret_cast<const float4*>(&Bs[buf][k][tx * 8 + 4]);
#pragma unroll
            for (int r = 0; r < 8; ++r)
#pragma unroll
                for (int c = 0; c < 8; ++c)
                    acc[r][c] = fmaf(a_[r], b_[c], acc[r][c]);
        }
        if (kt + 1 < nk) {
            *(float4*)&As[buf ^ 1][lr][lc] = a4;
            *(float4*)&Bs[buf ^ 1][lr][lc] = b4;
            __syncthreads();
            buf ^= 1;
        }
    }

    const float* ResB = Res ? Res + (long long)blockIdx.z * sRes : nullptr;
#pragma unroll
    for (int r = 0; r < 8; ++r) {
        long long row = (long long)(m0 + ty * 8 + r);
        float* cp = Cb + row * Nn + n0 + tx * 8;
        float4 v0 = make_float4(acc[r][0], acc[r][1], acc[r][2], acc[r][3]);
        float4 v1 = make_float4(acc[r][4], acc[r][5], acc[r][6], acc[r][7]);
        if (ResB) {
            const float* rp = ResB + row * Nn + n0 + tx * 8;
            float4 q0 = *(const float4*)rp;
            float4 q1 = *(const float4*)(rp + 4);
            v0.x += q0.x; v0.y += q0.y; v0.z += q0.z; v0.w += q0.w;
            v1.x += q1.x; v1.y += q1.y; v1.z += q1.z; v1.w += q1.w;
        }
        *(float4*)cp       = v0;
        *(float4*)(cp + 4) = v1;
    }
}

// ---------------- column softmax over LT (in-place) -------------------------
// LT[b][t][i]: for each column i, softmax over t<=i; zero-fill t>i.
__global__ void softmax_cols(float* __restrict__ LT, int Nn) {
    int b = blockIdx.y;
    int i = blockIdx.x * 128 + threadIdx.x;
    int tx = threadIdx.x, ty = threadIdx.y;
    float* L = LT + (long long)b * Nn * Nn;

    __shared__ float red[8][128];

    // pass 1: max over t <= i
    float m = -1e30f;
    for (int t = ty; t < Nn; t += 8)
        if (t <= i) m = fmaxf(m, L[(long long)t * Nn + i]);
    red[ty][tx] = m;
    __syncthreads();
    if (ty == 0) {
        float mm = red[0][tx];
#pragma unroll
        for (int r = 1; r < 8; ++r) mm = fmaxf(mm, red[r][tx]);
        red[0][tx] = mm;
    }
    __syncthreads();
    m = red[0][tx];
    __syncthreads();

    // pass 2: sum of exp
    float s = 0.f;
    for (int t = ty; t < Nn; t += 8)
        if (t <= i) s += __expf(L[(long long)t * Nn + i] - m);
    red[ty][tx] = s;
    __syncthreads();
    if (ty == 0) {
        float ss = red[0][tx];
#pragma unroll
        for (int r = 1; r < 8; ++r) ss += red[r][tx];
        red[0][tx] = ss;
    }
    __syncthreads();
    float inv = 1.f / red[0][tx];

    // pass 3: normalize + zero upper region
    for (int t = ty; t < Nn; t += 8) {
        long long idx = (long long)t * Nn + i;
        L[idx] = (t <= i) ? __expf(L[idx] - m) * inv : 0.f;
    }
}

// ---------------- launch ----------------------------------------------------
extern "C" void kernel_launch(void* const* d_in, const int* in_sizes, int n_in,
                              void* d_out, int out_size) {
    const float* X   = (const float*)d_in[0];
    const float* W_Q = (const float*)d_in[1];
    const float* W_K = (const float*)d_in[2];
    const float* W_V = (const float*)d_in[3];
    const float* W_O = (const float*)d_in[4];
    float* out = (float*)d_out;

    float *WQT, *WKT, *MT, *q, *kk, *XT, *ctx, *LT;
    cudaGetSymbolAddress((void**)&WQT, g_WQT);
    cudaGetSymbolAddress((void**)&WKT, g_WKT);
    cudaGetSymbolAddress((void**)&MT,  g_MT);
    cudaGetSymbolAddress((void**)&q,   g_q);
    cudaGetSymbolAddress((void**)&kk,  g_kk);
    cudaGetSymbolAddress((void**)&XT,  g_XT);
    cudaGetSymbolAddress((void**)&ctx, g_ctx);
    cudaGetSymbolAddress((void**)&LT,  g_LT);

    const long long sX  = (long long)DDIM * NSEQ;
    const long long sQ  = (long long)KDIM * NSEQ;
    const long long sXT = (long long)NSEQ * DDIM;
    const long long sL  = (long long)NSEQ * NSEQ;

    dim3 tb(32, 8);
    // weight transposes: (K,D) -> (D,K)
    transpose32<<<dim3(DDIM / 32, KDIM / 32, 1), tb>>>(W_Q, WQT, KDIM, DDIM, 0, 0);
    transpose32<<<dim3(DDIM / 32, KDIM / 32, 1), tb>>>(W_K, WKT, KDIM, DDIM, 0, 0);
    // X transpose per batch: (D,N) -> (N,D)
    transpose32<<<dim3(NSEQ / 32, DDIM / 32, BATCH), tb>>>(X, XT, DDIM, NSEQ, sX, sXT);

    // q[b][k][i] = sum_d WQT[d][k] X[b][d][i]
    tn_gemm<<<dim3(NSEQ / BN, KDIM / BM, BATCH), 256>>>(
        WQT, X, q, nullptr, KDIM, NSEQ, DDIM, 0, sX, sQ, 0, 0);
    tn_gemm<<<dim3(NSEQ / BN, KDIM / BM, BATCH), 256>>>(
        WKT, X, kk, nullptr, KDIM, NSEQ, DDIM, 0, sX, sQ, 0, 0);

    // MT[e][d] = sum_k W_V[k][e] W_O[k][d]   (= (W_O^T W_V)^T)
    tn_gemm<<<dim3(DDIM / BN, DDIM / BM, 1), 256>>>(
        W_V, W_O, MT, nullptr, DDIM, DDIM, KDIM, 0, 0, 0, 0, 0);

    // LT[b][t][i] = sum_k kk[b][k][t] q[b][k][i]  (only t<=i needed -> causal skip)
    tn_gemm<<<dim3(NSEQ / BN, NSEQ / BM, BATCH), 256>>>(
        kk, q, LT, nullptr, NSEQ, NSEQ, KDIM, sQ, sQ, sL, 0, 1);

    // A^T in-place
    softmax_cols<<<dim3(NSEQ / 128, BATCH), dim3(128, 8)>>>(LT, NSEQ);

    // ctx[b][e][i] = sum_t XT[b][t][e] AT[b][t][i]
    tn_gemm<<<dim3(NSEQ / BN, DDIM / BM, BATCH), 256>>>(
        XT, LT, ctx, nullptr, DDIM, NSEQ, NSEQ, sXT, sL, sX, 0, 0);

    // out[b][d][i] = X[b][d][i] + sum_e MT[e][d] ctx[b][e][i]
    tn_gemm<<<dim3(NSEQ / BN, DDIM / BM, BATCH), 256>>>(
        MT, ctx, out, X, DDIM, NSEQ, DDIM, 0, sX, sX, sX, 0);
}

// round 5
// speedup vs baseline: 1.3609x; 1.3609x over previous
#include <cuda_runtime.h>
#include <cuda_bf16.h>
#include <cstdint>

#define BATCH 4
#define DDIM  1024
#define NSEQ  2048
#define KDIM  1024

// ---------------- scratch (device globals) ----------------------------------
__device__ float g_XT  [BATCH * NSEQ * DDIM];   // (b, i, d) d-contig
__device__ float g_WOT [DDIM * KDIM];           // (d, k) k-contig
__device__ float g_WVT [DDIM * KDIM];           // (e, k) k-contig
__device__ float g_M   [DDIM * DDIM];           // M'[d][e] = sum_k WO[k][d] WV[k][e]
__device__ float g_q   [BATCH * NSEQ * KDIM];   // (b, i, k) k-contig
__device__ float g_kk  [BATCH * NSEQ * KDIM];   // (b, j, k) k-contig
__device__ float g_L   [BATCH * NSEQ * NSEQ];   // (b, i, j) logits -> A (row-major)
__device__ float g_ctxT[BATCH * NSEQ * DDIM];   // (b, i, e) e-contig

// ---------------- transpose: out[c][r] = in[r][c] ---------------------------
__global__ void transpose32(const float* __restrict__ in, float* __restrict__ out,
                            int rows, int cols, long long sIn, long long sOut) {
    __shared__ float tile[32][33];
    const float* I = in  + (long long)blockIdx.z * sIn;
    float*       O = out + (long long)blockIdx.z * sOut;
    int r0 = blockIdx.y * 32, c0 = blockIdx.x * 32;
    int x = threadIdx.x, y = threadIdx.y;
#pragma unroll
    for (int j = y; j < 32; j += 8)
        tile[j][x] = I[(long long)(r0 + j) * cols + c0 + x];
    __syncthreads();
#pragma unroll
    for (int j = y; j < 32; j += 8)
        O[(long long)(c0 + j) * rows + r0 + x] = tile[x][j];
}

// ---------------- helpers ----------------------------------------------------
__device__ __forceinline__ uint32_t smem_u32(const void* p) {
    uint32_t a;
    asm("{ .reg .u64 t; cvta.to.shared.u64 t, %1; cvt.u32.u64 %0, t; }" : "=r"(a) : "l"(p));
    return a;
}

__device__ __forceinline__ void ldsm4(uint32_t* r, uint32_t addr) {
    asm volatile("ldmatrix.sync.aligned.m8n8.x4.shared.b16 {%0,%1,%2,%3}, [%4];"
                 : "=r"(r[0]), "=r"(r[1]), "=r"(r[2]), "=r"(r[3]) : "r"(addr));
}

__device__ __forceinline__ void mma16816(float* d, const uint32_t* a, const uint32_t* b) {
    asm volatile(
        "mma.sync.aligned.m16n8k16.row.col.f32.bf16.bf16.f32 "
        "{%0,%1,%2,%3}, {%4,%5,%6,%7}, {%8,%9}, {%0,%1,%2,%3};"
        : "+f"(d[0]), "+f"(d[1]), "+f"(d[2]), "+f"(d[3])
        : "r"(a[0]), "r"(a[1]), "r"(a[2]), "r"(a[3]), "r"(b[0]), "r"(b[1]));
}

// pack 8 floats -> hi/lo bf16 uint4 chunks
__device__ __forceinline__ void cvt8(float4 a, float4 b, uint4& hi, uint4& lo) {
    float f[8] = {a.x, a.y, a.z, a.w, b.x, b.y, b.z, b.w};
    uint32_t h[4], l[4];
#pragma unroll
    for (int j = 0; j < 4; ++j) {
        __nv_bfloat16 h0 = __float2bfloat16(f[2 * j]);
        __nv_bfloat16 h1 = __float2bfloat16(f[2 * j + 1]);
        float r0 = f[2 * j]     - __bfloat162float(h0);
        float r1 = f[2 * j + 1] - __bfloat162float(h1);
        __nv_bfloat16 l0 = __float2bfloat16(r0);
        __nv_bfloat16 l1 = __float2bfloat16(r1);
        h[j] = (uint32_t)__bfloat16_as_ushort(h0) | ((uint32_t)__bfloat16_as_ushort(h1) << 16);
        l[j] = (uint32_t)__bfloat16_as_ushort(l0) | ((uint32_t)__bfloat16_as_ushort(l1) << 16);
    }
    hi = make_uint4(h[0], h[1], h[2], h[3]);
    lo = make_uint4(l[0], l[1], l[2], l[3]);
}

// ---------------- HMMA NT GEMM: C[m][n] = sum_k A[m][k]*B[n][k] --------------
// A: M x Kk (ld=Kk), B: N x Kk (ld=Kk), C: M x N (+ optional residual).
// bf16 hi/lo split, 3 passes (hh, hl, lh), fp32 accumulate.
#define TM 128
#define TN 128
#define KC 32
#define TILE_B 8192            // 128 rows x 64 bytes (swizzled)
#define STAGE_B (4 * TILE_B)   // Ahi, Alo, Bhi, Blo
#define SMEM_TOTAL (2 * STAGE_B)

__global__ void __launch_bounds__(256, 1)
tc_gemm(const float* __restrict__ A, const float* __restrict__ B,
        float* __restrict__ C, const float* __restrict__ Res,
        int M, int N, int Kk,
        long long sA, long long sB, long long sC, long long sRes, int causal) {
    int m0 = blockIdx.y * TM;
    int n0 = blockIdx.x * TN;
    if (causal && n0 > m0 + TM - 1) return;   // only cols j <= i needed

    extern __shared__ char sm[];
    uint32_t sb = smem_u32(sm);

    int tid = threadIdx.x;
    int lane = tid & 31, wid = tid >> 5;
    int wm = wid & 1, wn = wid >> 1;          // warp tile: 64(m) x 32(n)

    const float* Ab = A + (long long)blockIdx.z * sA;
    const float* Bb = B + (long long)blockIdx.z * sB;
    float*       Cb = C + (long long)blockIdx.z * sC;

    // staging mapping: row = tid&127, half h = tid>>7 (16 floats each)
    int srow = tid & 127, sh = tid >> 7;
    uint32_t sRowOff = (uint32_t)srow * 64;
    int ssw = (srow >> 1) & 3;
    uint32_t sc0 = (uint32_t)(((2 * sh)     ^ ssw) << 4);
    uint32_t sc1 = (uint32_t)(((2 * sh + 1) ^ ssw) << 4);
    const float* gA = Ab + (long long)(m0 + srow) * Kk + sh * 16;
    const float* gB = Bb + (long long)(n0 + srow) * Kk + sh * 16;

    // ldmatrix per-lane addressing
    int ra = wm * 64 + (lane & 15);
    int abit = lane >> 4;
    uint32_t aRow = (uint32_t)ra * 64;
    int swA = (ra >> 1) & 3;
    uint32_t colA[2] = { (uint32_t)(((0 + abit) ^ swA) << 4),
                         (uint32_t)(((2 + abit) ^ swA) << 4) };
    int rb = wn * 32 + ((lane >> 4) << 3) + (lane & 7);
    int bbit = (lane >> 3) & 1;
    uint32_t bRow = (uint32_t)rb * 64;
    int swB = (rb >> 1) & 3;
    uint32_t colB[2] = { (uint32_t)(((0 + bbit) ^ swB) << 4),
                         (uint32_t)(((2 + bbit) ^ swB) << 4) };

    float acc[4][4][4];
#pragma unroll
    for (int mt = 0; mt < 4; ++mt)
#pragma unroll
        for (int nt = 0; nt < 4; ++nt)
#pragma unroll
            for (int r = 0; r < 4; ++r) acc[mt][nt][r] = 0.f;

    const int nc = Kk / KC;

    // prologue: stage chunk 0 into buffer 0
    {
        float4 a0 = *(const float4*)(gA + 0), a1 = *(const float4*)(gA + 4);
        float4 a2 = *(const float4*)(gA + 8), a3 = *(const float4*)(gA + 12);
        float4 b0 = *(const float4*)(gB + 0), b1 = *(const float4*)(gB + 4);
        float4 b2 = *(const float4*)(gB + 8), b3 = *(const float4*)(gB + 12);
        uint4 hi, lo;
        char* st = sm;
        cvt8(a0, a1, hi, lo);
        *(uint4*)(st + 0 * TILE_B + sRowOff + sc0) = hi;
        *(uint4*)(st + 1 * TILE_B + sRowOff + sc0) = lo;
        cvt8(a2, a3, hi, lo);
        *(uint4*)(st + 0 * TILE_B + sRowOff + sc1) = hi;
        *(uint4*)(st + 1 * TILE_B + sRowOff + sc1) = lo;
        cvt8(b0, b1, hi, lo);
        *(uint4*)(st + 2 * TILE_B + sRowOff + sc0) = hi;
        *(uint4*)(st + 3 * TILE_B + sRowOff + sc0) = lo;
        cvt8(b2, b3, hi, lo);
        *(uint4*)(st + 2 * TILE_B + sRowOff + sc1) = hi;
        *(uint4*)(st + 3 * TILE_B + sRowOff + sc1) = lo;
    }
    __syncthreads();

    for (int c = 0; c < nc; ++c) {
        int buf = c & 1;
        // prefetch next chunk g->reg
        float4 pa0, pa1, pa2, pa3, pb0, pb1, pb2, pb3;
        if (c + 1 < nc) {
            const float* nA = gA + (long long)(c + 1) * KC;
            const float* nB = gB + (long long)(c + 1) * KC;
            pa0 = *(const float4*)(nA + 0);  pa1 = *(const float4*)(nA + 4);
            pa2 = *(const float4*)(nA + 8);  pa3 = *(const float4*)(nA + 12);
            pb0 = *(const float4*)(nB + 0);  pb1 = *(const float4*)(nB + 4);
            pb2 = *(const float4*)(nB + 8);  pb3 = *(const float4*)(nB + 12);
        }

        uint32_t bAhi = sb + buf * STAGE_B + 0 * TILE_B;
        uint32_t bAlo = sb + buf * STAGE_B + 1 * TILE_B;
        uint32_t bBhi = sb + buf * STAGE_B + 2 * TILE_B;
        uint32_t bBlo = sb + buf * STAGE_B + 3 * TILE_B;

#pragma unroll
        for (int kk2 = 0; kk2 < 2; ++kk2) {
            uint32_t ah[4][4], bh[4][2];
#pragma unroll
            for (int mt = 0; mt < 4; ++mt)
                ldsm4(ah[mt], bAhi + aRow + mt * 1024 + colA[kk2]);
#pragma unroll
            for (int jp = 0; jp < 2; ++jp) {
                uint32_t r[4];
                ldsm4(r, bBhi + bRow + jp * 1024 + colB[kk2]);
                bh[2 * jp][0] = r[0]; bh[2 * jp][1] = r[1];
                bh[2 * jp + 1][0] = r[2]; bh[2 * jp + 1][1] = r[3];
            }
#pragma unroll
            for (int mt = 0; mt < 4; ++mt)
#pragma unroll
                for (int nt = 0; nt < 4; ++nt)
                    mma16816(acc[mt][nt], ah[mt], bh[nt]);

            uint32_t bl[4][2];
#pragma unroll
            for (int jp = 0; jp < 2; ++jp) {
                uint32_t r[4];
                ldsm4(r, bBlo + bRow + jp * 1024 + colB[kk2]);
                bl[2 * jp][0] = r[0]; bl[2 * jp][1] = r[1];
                bl[2 * jp + 1][0] = r[2]; bl[2 * jp + 1][1] = r[3];
            }
#pragma unroll
            for (int mt = 0; mt < 4; ++mt)
#pragma unroll
                for (int nt = 0; nt < 4; ++nt)
                    mma16816(acc[mt][nt], ah[mt], bl[nt]);

            uint32_t al[4][4];
#pragma unroll
            for (int mt = 0; mt < 4; ++mt)
                ldsm4(al[mt], bAlo + aRow + mt * 1024 + colA[kk2]);
#pragma unroll
            for (int mt = 0; mt < 4; ++mt)
#pragma unroll
                for (int nt = 0; nt < 4; ++nt)
                    mma16816(acc[mt][nt], al[mt], bh[nt]);
        }
        __syncthreads();

        if (c + 1 < nc) {
            char* st = sm + (buf ^ 1) * STAGE_B;
            uint4 hi, lo;
            cvt8(pa0, pa1, hi, lo);
            *(uint4*)(st + 0 * TILE_B + sRowOff + sc0) = hi;
            *(uint4*)(st + 1 * TILE_B + sRowOff + sc0) = lo;
            cvt8(pa2, pa3, hi, lo);
            *(uint4*)(st + 0 * TILE_B + sRowOff + sc1) = hi;
            *(uint4*)(st + 1 * TILE_B + sRowOff + sc1) = lo;
            cvt8(pb0, pb1, hi, lo);
            *(uint4*)(st + 2 * TILE_B + sRowOff + sc0) = hi;
            *(uint4*)(st + 3 * TILE_B + sRowOff + sc0) = lo;
            cvt8(pb2, pb3, hi, lo);
            *(uint4*)(st + 2 * TILE_B + sRowOff + sc1) = hi;
            *(uint4*)(st + 3 * TILE_B + sRowOff + sc1) = lo;
            __syncthreads();
        }
    }

    // epilogue: thread (mt,nt): rows m0+wm*64+mt*16+(lane>>2)(+8), cols n0+wn*32+nt*8+2*(lane&3)
    int er = lane >> 2, ec = (lane & 3) * 2;
    const float* ResB = Res ? Res + (long long)blockIdx.z * sRes : nullptr;
#pragma unroll
    for (int mt = 0; mt < 4; ++mt) {
#pragma unroll
        for (int nt = 0; nt < 4; ++nt) {
            long long r0 = (long long)(m0 + wm * 64 + mt * 16 + er);
            int col = n0 + wn * 32 + nt * 8 + ec;
            float* cp0 = Cb + r0 * N + col;
            float* cp1 = cp0 + 8LL * N;
            float2 v0 = make_float2(acc[mt][nt][0], acc[mt][nt][1]);
            float2 v1 = make_float2(acc[mt][nt][2], acc[mt][nt][3]);
            if (ResB) {
                const float2 q0 = *(const float2*)(ResB + r0 * N + col);
                const float2 q1 = *(const float2*)(ResB + (r0 + 8) * N + col);
                v0.x += q0.x; v0.y += q0.y;
                v1.x += q1.x; v1.y += q1.y;
            }
            *(float2*)cp0 = v0;
            *(float2*)cp1 = v1;
        }
    }
}

// ---------------- row softmax over L (in-place), causal ---------------------
__global__ void softmax_rows(float* __restrict__ L, int Nn) {
    int b = blockIdx.y, i = blockIdx.x;
    float* row = L + ((long long)b * Nn + i) * Nn;
    int nv = i + 1;
    int t = threadIdx.x;
    __shared__ float red[256];

    float m = -1e30f;
    for (int j = t; j < nv; j += 256) m = fmaxf(m, row[j]);
    red[t] = m; __syncthreads();
    for (int s = 128; s > 0; s >>= 1) {
        if (t < s) red[t] = fmaxf(red[t], red[t + s]);
        __syncthreads();
    }
    m = red[0]; __syncthreads();

    float ssum = 0.f;
    for (int j = t; j < nv; j += 256) ssum += __expf(row[j] - m);
    red[t] = ssum; __syncthreads();
    for (int s = 128; s > 0; s >>= 1) {
        if (t < s) red[t] += red[t + s];
        __syncthreads();
    }
    float inv = 1.f / red[0];

    for (int j = t; j < nv; j += 256) row[j] = __expf(row[j] - m) * inv;
    for (int j = nv + t; j < Nn; j += 256) row[j] = 0.f;
}

// ---------------- launch ----------------------------------------------------
extern "C" void kernel_launch(void* const* d_in, const int* in_sizes, int n_in,
                              void* d_out, int out_size) {
    const float* X   = (const float*)d_in[0];
    const float* W_Q = (const float*)d_in[1];
    const float* W_K = (const float*)d_in[2];
    const float* W_V = (const float*)d_in[3];
    const float* W_O = (const float*)d_in[4];
    float* out = (float*)d_out;

    float *XT, *WOT, *WVT, *Mm, *q, *kk, *L, *ctxT;
    cudaGetSymbolAddress((void**)&XT,  g_XT);
    cudaGetSymbolAddress((void**)&WOT, g_WOT);
    cudaGetSymbolAddress((void**)&WVT, g_WVT);
    cudaGetSymbolAddress((void**)&Mm,  g_M);
    cudaGetSymbolAddress((void**)&q,   g_q);
    cudaGetSymbolAddress((void**)&kk,  g_kk);
    cudaGetSymbolAddress((void**)&L,   g_L);
    cudaGetSymbolAddress((void**)&ctxT, g_ctxT);

    cudaFuncSetAttribute(tc_gemm, cudaFuncAttributeMaxDynamicSharedMemorySize, SMEM_TOTAL);

    const long long sX  = (long long)DDIM * NSEQ;
    const long long sXT = (long long)NSEQ * DDIM;
    const long long sQ  = (long long)NSEQ * KDIM;
    const long long sL  = (long long)NSEQ * NSEQ;

    dim3 tb(32, 8);
    transpose32<<<dim3(NSEQ / 32, DDIM / 32, BATCH), tb>>>(X, XT, DDIM, NSEQ, sX, sXT);
    transpose32<<<dim3(DDIM / 32, KDIM / 32, 1), tb>>>(W_O, WOT, KDIM, DDIM, 0, 0);
    transpose32<<<dim3(DDIM / 32, KDIM / 32, 1), tb>>>(W_V, WVT, KDIM, DDIM, 0, 0);

    // q[i][k] = sum_d XT[i][d] * W_Q[k][d]
    tc_gemm<<<dim3(KDIM / TN, NSEQ / TM, BATCH), 256, SMEM_TOTAL>>>(
        XT, W_Q, q, nullptr, NSEQ, KDIM, DDIM, sXT, 0, sQ, 0, 0);
    tc_gemm<<<dim3(KDIM / TN, NSEQ / TM, BATCH), 256, SMEM_TOTAL>>>(
        XT, W_K, kk, nullptr, NSEQ, KDIM, DDIM, sXT, 0, sQ, 0, 0);

    // M'[d][e] = sum_k WOT[d][k] * WVT[e][k]
    tc_gemm<<<dim3(DDIM / TN, DDIM / TM, 1), 256, SMEM_TOTAL>>>(
        WOT, WVT, Mm, nullptr, DDIM, DDIM, KDIM, 0, 0, 0, 0, 0);

    // L[i][j] = sum_k q[i][k] * kk[j][k]  (causal: j <= i)
    tc_gemm<<<dim3(NSEQ / TN, NSEQ / TM, BATCH), 256, SMEM_TOTAL>>>(
        q, kk, L, nullptr, NSEQ, NSEQ, KDIM, sQ, sQ, sL, 0, 1);

    softmax_rows<<<dim3(NSEQ, BATCH), 256>>>(L, NSEQ);

    // ctxT[i][e] = sum_t L[i][t] * X[e][t]
    tc_gemm<<<dim3(DDIM / TN, NSEQ / TM, BATCH), 256, SMEM_TOTAL>>>(
        L, X, ctxT, nullptr, NSEQ, DDIM, NSEQ, sL, sX, sXT, 0, 0);

    // out[d][i] = X[d][i] + sum_e M'[d][e] * ctxT[i][e]
    tc_gemm<<<dim3(NSEQ / TN, DDIM / TM, BATCH), 256, SMEM_TOTAL>>>(
        Mm, ctxT, out, X, DDIM, NSEQ, DDIM, 0, sXT, sX, sX, 0);
}

// round 6
// speedup vs baseline: 2.2289x; 1.6378x over previous
#include <cuda_runtime.h>
#include <cuda_bf16.h>
#include <cstdint>

#define BATCH 4
#define DDIM  1024
#define NSEQ  2048
#define KDIM  1024

typedef __nv_bfloat16 bf16;

// ---------------- scratch (device globals; zero-init bss) -------------------
__device__ bf16 g_Xhi [BATCH * DDIM * NSEQ], g_Xlo [BATCH * DDIM * NSEQ];   // (b,d,n)
__device__ bf16 g_XThi[BATCH * NSEQ * DDIM], g_XTlo[BATCH * NSEQ * DDIM];   // (b,i,d)
__device__ bf16 g_WQhi[KDIM * DDIM], g_WQlo[KDIM * DDIM];                   // (k,d)
__device__ bf16 g_WKhi[KDIM * DDIM], g_WKlo[KDIM * DDIM];
__device__ bf16 g_WOThi[DDIM * KDIM], g_WOTlo[DDIM * KDIM];                 // (d,k)
__device__ bf16 g_WVThi[DDIM * KDIM], g_WVTlo[DDIM * KDIM];                 // (e,k)
__device__ bf16 g_qhi [BATCH * NSEQ * KDIM], g_qlo [BATCH * NSEQ * KDIM];   // (b,i,k)
__device__ bf16 g_khi [BATCH * NSEQ * KDIM], g_klo [BATCH * NSEQ * KDIM];   // (b,j,k)
__device__ bf16 g_Mhi [DDIM * DDIM], g_Mlo [DDIM * DDIM];                   // (d,e)
__device__ float g_L  [BATCH * NSEQ * NSEQ];                                // logits fp32
__device__ bf16 g_Ahi [BATCH * NSEQ * NSEQ], g_Alo [BATCH * NSEQ * NSEQ];   // softmax out
__device__ bf16 g_cthi[BATCH * NSEQ * DDIM], g_ctlo[BATCH * NSEQ * DDIM];   // (b,i,e)

// ---------------- helpers ----------------------------------------------------
__device__ __forceinline__ uint32_t smem_u32(const void* p) {
    uint32_t a;
    asm("{ .reg .u64 t; cvta.to.shared.u64 t, %1; cvt.u32.u64 %0, t; }" : "=r"(a) : "l"(p));
    return a;
}
__device__ __forceinline__ void ldsm4(uint32_t* r, uint32_t addr) {
    asm volatile("ldmatrix.sync.aligned.m8n8.x4.shared.b16 {%0,%1,%2,%3}, [%4];"
                 : "=r"(r[0]), "=r"(r[1]), "=r"(r[2]), "=r"(r[3]) : "r"(addr));
}
__device__ __forceinline__ void mma16816(float* d, const uint32_t* a, const uint32_t* b) {
    asm volatile(
        "mma.sync.aligned.m16n8k16.row.col.f32.bf16.bf16.f32 "
        "{%0,%1,%2,%3}, {%4,%5,%6,%7}, {%8,%9}, {%0,%1,%2,%3};"
        : "+f"(d[0]), "+f"(d[1]), "+f"(d[2]), "+f"(d[3])
        : "r"(a[0]), "r"(a[1]), "r"(a[2]), "r"(a[3]), "r"(b[0]), "r"(b[1]));
}
__device__ __forceinline__ void cpasync16(uint32_t dst, const void* src) {
    asm volatile("cp.async.cg.shared.global [%0], [%1], 16;" :: "r"(dst), "l"(src));
}
__device__ __forceinline__ void cp_commit() { asm volatile("cp.async.commit_group;"); }
__device__ __forceinline__ void cp_wait1()  { asm volatile("cp.async.wait_group 1;"); }

__device__ __forceinline__ uint32_t pack_hi(float a, float b) {
    bf16 h0 = __float2bfloat16(a), h1 = __float2bfloat16(b);
    return (uint32_t)__bfloat16_as_ushort(h0) | ((uint32_t)__bfloat16_as_ushort(h1) << 16);
}
__device__ __forceinline__ uint32_t pack_lo(float a, float b) {
    bf16 h0 = __float2bfloat16(a), h1 = __float2bfloat16(b);
    float l0 = a - __bfloat162float(h0), l1 = b - __bfloat162float(h1);
    return (uint32_t)__bfloat16_as_ushort(__float2bfloat16(l0)) |
           ((uint32_t)__bfloat16_as_ushort(__float2bfloat16(l1)) << 16);
}

// ---------------- convert fp32 -> bf16 hi/lo --------------------------------
__global__ void convert_hl(const float* __restrict__ in, bf16* __restrict__ hi,
                           bf16* __restrict__ lo, long long n) {
    long long i = ((long long)blockIdx.x * blockDim.x + threadIdx.x) * 4;
    if (i >= n) return;
    float4 v = *(const float4*)(in + i);
    *(uint2*)(hi + i) = make_uint2(pack_hi(v.x, v.y), pack_hi(v.z, v.w));
    *(uint2*)(lo + i) = make_uint2(pack_lo(v.x, v.y), pack_lo(v.z, v.w));
}

// ---------------- transpose fp32 -> bf16 hi/lo: out[c][r] = in[r][c] --------
__global__ void transpose_hl(const float* __restrict__ in, bf16* __restrict__ hi,
                             bf16* __restrict__ lo, int rows, int cols,
                             long long sIn, long long sOut) {
    __shared__ float tile[32][33];
    const float* I = in + (long long)blockIdx.z * sIn;
    int r0 = blockIdx.y * 32, c0 = blockIdx.x * 32;
    int x = threadIdx.x, y = threadIdx.y;
#pragma unroll
    for (int j = y; j < 32; j += 8)
        tile[j][x] = I[(long long)(r0 + j) * cols + c0 + x];
    __syncthreads();
    long long zo = (long long)blockIdx.z * sOut;
#pragma unroll
    for (int j = y; j < 32; j += 8) {
        float v = tile[x][j];
        long long o = zo + (long long)(c0 + j) * rows + r0 + x;
        bf16 h = __float2bfloat16(v);
        hi[o] = h;
        lo[o] = __float2bfloat16(v - __bfloat162float(h));
    }
}

// ---------------- bf16 hi/lo HMMA NT GEMM -----------------------------------
// C[m][n] = sum_k A[m][k]*B[n][k], A/B given as hi/lo bf16 (ld=Kk).
// Output: fp32 (+res) if Cf != null, else bf16 hi/lo pair.
#define TM 128
#define TN 128
#define KC 32
#define TILE_B 8192            // 128 rows x 64B (swizzled)
#define STAGE_B (4 * TILE_B)   // Ahi, Alo, Bhi, Blo
#define STAGES 3
#define GSMEM (STAGES * STAGE_B)

__global__ void __launch_bounds__(256, 2)
hgemm(const bf16* __restrict__ Ahi_, const bf16* __restrict__ Alo_,
      const bf16* __restrict__ Bhi_, const bf16* __restrict__ Blo_,
      float* __restrict__ Cf, bf16* __restrict__ Chi, bf16* __restrict__ Clo,
      const float* __restrict__ Res,
      int M, int N, int Kk,
      long long sA, long long sB, long long sC, long long sRes, int causal) {
    int m0 = blockIdx.y * TM;
    int n0 = blockIdx.x * TN;
    if (causal && n0 > m0 + TM - 1) return;

    extern __shared__ char sm[];
    uint32_t sb = smem_u32(sm);
    int tid = threadIdx.x, lane = tid & 31, wid = tid >> 5;
    int wm = wid & 1, wn = wid >> 1;
    long long z = blockIdx.z;

    // per-thread cp.async mapping: 2 ops x 4 tiles; op j covers (row, 16B seg)
    const bf16* gp[8];
    uint32_t so[2];
#pragma unroll
    for (int j = 0; j < 2; ++j) {
        int idx = tid * 2 + j;
        int row = idx >> 2, seg = idx & 3;
        so[j] = (uint32_t)(row * 64 + ((seg ^ ((row >> 1) & 3)) << 4));
        gp[j * 4 + 0] = Ahi_ + z * sA + (long long)(m0 + row) * Kk + seg * 8;
        gp[j * 4 + 1] = Alo_ + z * sA + (long long)(m0 + row) * Kk + seg * 8;
        gp[j * 4 + 2] = Bhi_ + z * sB + (long long)(n0 + row) * Kk + seg * 8;
        gp[j * 4 + 3] = Blo_ + z * sB + (long long)(n0 + row) * Kk + seg * 8;
    }

    // ldmatrix addressing (64B rows, 16B-chunk XOR swizzle)
    int ra = wm * 64 + (lane & 15);
    int abit = lane >> 4;
    uint32_t aRow = (uint32_t)ra * 64;
    int swA = (ra >> 1) & 3;
    uint32_t colA[2] = { (uint32_t)(((0 + abit) ^ swA) << 4),
                         (uint32_t)(((2 + abit) ^ swA) << 4) };
    int rb = wn * 32 + ((lane >> 4) << 3) + (lane & 7);
    int bbit = (lane >> 3) & 1;
    uint32_t bRow = (uint32_t)rb * 64;
    int swB = (rb >> 1) & 3;
    uint32_t colB[2] = { (uint32_t)(((0 + bbit) ^ swB) << 4),
                         (uint32_t)(((2 + bbit) ^ swB) << 4) };

    float acc[4][4][4];
#pragma unroll
    for (int mt = 0; mt < 4; ++mt)
#pragma unroll
        for (int nt = 0; nt < 4; ++nt)
#pragma unroll
            for (int r = 0; r < 4; ++r) acc[mt][nt][r] = 0.f;

    const int nc = Kk / KC;

    // prologue: stage chunks 0,1
#pragma unroll
    for (int s = 0; s < STAGES - 1; ++s) {
        long long off = (long long)s * KC;
#pragma unroll
        for (int j = 0; j < 2; ++j)
#pragma unroll
            for (int T = 0; T < 4; ++T)
                cpasync16(sb + s * STAGE_B + T * TILE_B + so[j], gp[j * 4 + T] + off);
        cp_commit();
    }

    for (int c = 0; c < nc; ++c) {
        cp_wait1();
        __syncthreads();
        // issue chunk c+2 into buffer (c+2)%3 (freed by compute of chunk c-1)
        if (c + 2 < nc) {
            int st = (c + 2) % STAGES;
            long long off = (long long)(c + 2) * KC;
#pragma unroll
            for (int j = 0; j < 2; ++j)
#pragma unroll
                for (int T = 0; T < 4; ++T)
                    cpasync16(sb + st * STAGE_B + T * TILE_B + so[j], gp[j * 4 + T] + off);
            cp_commit();
        } else {
            cp_commit();
        }

        uint32_t bA = sb + (c % STAGES) * STAGE_B;
        uint32_t bAhi = bA, bAlo = bA + TILE_B, bBhi = bA + 2 * TILE_B, bBlo = bA + 3 * TILE_B;

#pragma unroll
        for (int kk2 = 0; kk2 < 2; ++kk2) {
            uint32_t ah[4][4], bh[4][2];
#pragma unroll
            for (int mt = 0; mt < 4; ++mt)
                ldsm4(ah[mt], bAhi + aRow + mt * 1024 + colA[kk2]);
#pragma unroll
            for (int jp = 0; jp < 2; ++jp) {
                uint32_t r[4];
                ldsm4(r, bBhi + bRow + jp * 1024 + colB[kk2]);
                bh[2 * jp][0] = r[0]; bh[2 * jp][1] = r[1];
                bh[2 * jp + 1][0] = r[2]; bh[2 * jp + 1][1] = r[3];
            }
#pragma unroll
            for (int mt = 0; mt < 4; ++mt)
#pragma unroll
                for (int nt = 0; nt < 4; ++nt)
                    mma16816(acc[mt][nt], ah[mt], bh[nt]);

            uint32_t bl[4][2];
#pragma unroll
            for (int jp = 0; jp < 2; ++jp) {
                uint32_t r[4];
                ldsm4(r, bBlo + bRow + jp * 1024 + colB[kk2]);
                bl[2 * jp][0] = r[0]; bl[2 * jp][1] = r[1];
                bl[2 * jp + 1][0] = r[2]; bl[2 * jp + 1][1] = r[3];
            }
#pragma unroll
            for (int mt = 0; mt < 4; ++mt)
#pragma unroll
                for (int nt = 0; nt < 4; ++nt)
                    mma16816(acc[mt][nt], ah[mt], bl[nt]);

            uint32_t al[4][4];
#pragma unroll
            for (int mt = 0; mt < 4; ++mt)
                ldsm4(al[mt], bAlo + aRow + mt * 1024 + colA[kk2]);
#pragma unroll
            for (int mt = 0; mt < 4; ++mt)
#pragma unroll
                for (int nt = 0; nt < 4; ++nt)
                    mma16816(acc[mt][nt], al[mt], bh[nt]);
        }
    }

    // epilogue
    int er = lane >> 2, ec = (lane & 3) * 2;
    if (Cf) {
        float* Cb = Cf + z * sC;
        const float* Rb = Res ? Res + z * sRes : nullptr;
#pragma unroll
        for (int mt = 0; mt < 4; ++mt) {
#pragma unroll
            for (int nt = 0; nt < 4; ++nt) {
                long long r0 = (long long)(m0 + wm * 64 + mt * 16 + er);
                int col = n0 + wn * 32 + nt * 8 + ec;
                float2 v0 = make_float2(acc[mt][nt][0], acc[mt][nt][1]);
                float2 v1 = make_float2(acc[mt][nt][2], acc[mt][nt][3]);
                if (Rb) {
                    float2 q0 = *(const float2*)(Rb + r0 * N + col);
                    float2 q1 = *(const float2*)(Rb + (r0 + 8) * N + col);
                    v0.x += q0.x; v0.y += q0.y; v1.x += q1.x; v1.y += q1.y;
                }
                *(float2*)(Cb + r0 * N + col)       = v0;
                *(float2*)(Cb + (r0 + 8) * N + col) = v1;
            }
        }
    } else {
        bf16* Hb = Chi + z * sC;
        bf16* Lb = Clo + z * sC;
#pragma unroll
        for (int mt = 0; mt < 4; ++mt) {
#pragma unroll
            for (int nt = 0; nt < 4; ++nt) {
                long long r0 = (long long)(m0 + wm * 64 + mt * 16 + er);
                int col = n0 + wn * 32 + nt * 8 + ec;
#pragma unroll
                for (int h = 0; h < 2; ++h) {
                    float v0 = acc[mt][nt][2 * h], v1 = acc[mt][nt][2 * h + 1];
                    long long o = (r0 + 8 * h) * N + col;
                    *(uint32_t*)(Hb + o) = pack_hi(v0, v1);
                    *(uint32_t*)(Lb + o) = pack_lo(v0, v1);
                }
            }
        }
    }
}

// ---------------- row softmax: L fp32 -> A bf16 hi/lo, causal ---------------
__global__ void softmax_rows(const float* __restrict__ L, bf16* __restrict__ Ahi,
                             bf16* __restrict__ Alo, int Nn) {
    int b = blockIdx.y, i = blockIdx.x;
    const float* row = L + ((long long)b * Nn + i) * Nn;
    bf16* ah = Ahi + ((long long)b * Nn + i) * Nn;
    bf16* al = Alo + ((long long)b * Nn + i) * Nn;
    int nv = i + 1;
    int t = threadIdx.x;
    __shared__ float red[256];

    float m = -1e30f;
    for (int j = t; j < nv; j += 256) m = fmaxf(m, row[j]);
    red[t] = m; __syncthreads();
    for (int s = 128; s > 0; s >>= 1) {
        if (t < s) red[t] = fmaxf(red[t], red[t + s]);
        __syncthreads();
    }
    m = red[0]; __syncthreads();

    float ssum = 0.f;
    for (int j = t; j < nv; j += 256) ssum += __expf(row[j] - m);
    red[t] = ssum; __syncthreads();
    for (int s = 128; s > 0; s >>= 1) {
        if (t < s) red[t] += red[t + s];
        __syncthreads();
    }
    float inv = 1.f / red[0];

    for (int j = t; j < nv; j += 256) {
        float v = __expf(row[j] - m) * inv;
        bf16 h = __float2bfloat16(v);
        ah[j] = h;
        al[j] = __float2bfloat16(v - __bfloat162float(h));
    }
    bf16 zz = __float2bfloat16(0.f);
    for (int j = nv + t; j < Nn; j += 256) { ah[j] = zz; al[j] = zz; }
}

// ---------------- launch ----------------------------------------------------
extern "C" void kernel_launch(void* const* d_in, const int* in_sizes, int n_in,
                              void* d_out, int out_size) {
    const float* X   = (const float*)d_in[0];
    const float* W_Q = (const float*)d_in[1];
    const float* W_K = (const float*)d_in[2];
    const float* W_V = (const float*)d_in[3];
    const float* W_O = (const float*)d_in[4];
    float* out = (float*)d_out;

    bf16 *Xhi, *Xlo, *XThi, *XTlo, *WQhi, *WQlo, *WKhi, *WKlo;
    bf16 *WOThi, *WOTlo, *WVThi, *WVTlo, *qhi, *qlo, *khi, *klo;
    bf16 *Mhi, *Mlo, *Ahi, *Alo, *cthi, *ctlo;
    float* L;
    cudaGetSymbolAddress((void**)&Xhi, g_Xhi);   cudaGetSymbolAddress((void**)&Xlo, g_Xlo);
    cudaGetSymbolAddress((void**)&XThi, g_XThi); cudaGetSymbolAddress((void**)&XTlo, g_XTlo);
    cudaGetSymbolAddress((void**)&WQhi, g_WQhi); cudaGetSymbolAddress((void**)&WQlo, g_WQlo);
    cudaGetSymbolAddress((void**)&WKhi, g_WKhi); cudaGetSymbolAddress((void**)&WKlo, g_WKlo);
    cudaGetSymbolAddress((void**)&WOThi, g_WOThi); cudaGetSymbolAddress((void**)&WOTlo, g_WOTlo);
    cudaGetSymbolAddress((void**)&WVThi, g_WVThi); cudaGetSymbolAddress((void**)&WVTlo, g_WVTlo);
    cudaGetSymbolAddress((void**)&qhi, g_qhi);   cudaGetSymbolAddress((void**)&qlo, g_qlo);
    cudaGetSymbolAddress((void**)&khi, g_khi);   cudaGetSymbolAddress((void**)&klo, g_klo);
    cudaGetSymbolAddress((void**)&Mhi, g_Mhi);   cudaGetSymbolAddress((void**)&Mlo, g_Mlo);
    cudaGetSymbolAddress((void**)&Ahi, g_Ahi);   cudaGetSymbolAddress((void**)&Alo, g_Alo);
    cudaGetSymbolAddress((void**)&cthi, g_cthi); cudaGetSymbolAddress((void**)&ctlo, g_ctlo);
    cudaGetSymbolAddress((void**)&L, g_L);

    cudaFuncSetAttribute(hgemm, cudaFuncAttributeMaxDynamicSharedMemorySize, GSMEM);

    const long long sX  = (long long)DDIM * NSEQ;
    const long long sXT = (long long)NSEQ * DDIM;
    const long long sQ  = (long long)NSEQ * KDIM;
    const long long sL  = (long long)NSEQ * NSEQ;

    // input conversions
    convert_hl<<<(int)((long long)BATCH * sX / 4 / 256), 256>>>(X, Xhi, Xlo, (long long)BATCH * sX);
    convert_hl<<<(KDIM * DDIM / 4) / 256, 256>>>(W_Q, WQhi, WQlo, KDIM * DDIM);
    convert_hl<<<(KDIM * DDIM / 4) / 256, 256>>>(W_K, WKhi, WKlo, KDIM * DDIM);
    dim3 tb(32, 8);
    transpose_hl<<<dim3(NSEQ / 32, DDIM / 32, BATCH), tb>>>(X, XThi, XTlo, DDIM, NSEQ, sX, sXT);
    transpose_hl<<<dim3(DDIM / 32, KDIM / 32, 1), tb>>>(W_O, WOThi, WOTlo, KDIM, DDIM, 0, 0);
    transpose_hl<<<dim3(DDIM / 32, KDIM / 32, 1), tb>>>(W_V, WVThi, WVTlo, KDIM, DDIM, 0, 0);

    // q[i][k] = sum_d XT[i][d] * W_Q[k][d]   (bf16 out)
    hgemm<<<dim3(KDIM / TN, NSEQ / TM, BATCH), 256, GSMEM>>>(
        XThi, XTlo, WQhi, WQlo, nullptr, qhi, qlo, nullptr,
        NSEQ, KDIM, DDIM, sXT, 0, sQ, 0, 0);
    hgemm<<<dim3(KDIM / TN, NSEQ / TM, BATCH), 256, GSMEM>>>(
        XThi, XTlo, WKhi, WKlo, nullptr, khi, klo, nullptr,
        NSEQ, KDIM, DDIM, sXT, 0, sQ, 0, 0);

    // M'[d][e] = sum_k WOT[d][k] * WVT[e][k]   (bf16 out)
    hgemm<<<dim3(DDIM / TN, DDIM / TM, 1), 256, GSMEM>>>(
        WOThi, WOTlo, WVThi, WVTlo, nullptr, Mhi, Mlo, nullptr,
        DDIM, DDIM, KDIM, 0, 0, 0, 0, 0);

    // L[i][j] = sum_k q[i][k] * kk[j][k]  (fp32 out, causal)
    hgemm<<<dim3(NSEQ / TN, NSEQ / TM, BATCH), 256, GSMEM>>>(
        qhi, qlo, khi, klo, L, nullptr, nullptr, nullptr,
        NSEQ, NSEQ, KDIM, sQ, sQ, sL, 0, 1);

    softmax_rows<<<dim3(NSEQ, BATCH), 256>>>(L, Ahi, Alo, NSEQ);

    // ctxT[i][e] = sum_t A[i][t] * X[e][t]   (bf16 out)
    hgemm<<<dim3(DDIM / TN, NSEQ / TM, BATCH), 256, GSMEM>>>(
        Ahi, Alo, Xhi, Xlo, nullptr, cthi, ctlo, nullptr,
        NSEQ, DDIM, NSEQ, sL, sX, sXT, 0, 0);

    // out[d][i] = X[d][i] + sum_e M'[d][e] * ctxT[i][e]   (fp32 out + residual)
    hgemm<<<dim3(NSEQ / TN, DDIM / TM, BATCH), 256, GSMEM>>>(
        Mhi, Mlo, cthi, ctlo, out, nullptr, nullptr, X,
        DDIM, NSEQ, DDIM, 0, sXT, sX, sX, 0);
}

// round 7
// speedup vs baseline: 2.5765x; 1.1560x over previous
#include <cuda_runtime.h>
#include <cuda_bf16.h>
#include <cstdint>

#define BATCH 4
#define DDIM  1024
#define NSEQ  2048
#define KDIM  1024

typedef __nv_bfloat16 bf16;

// ---------------- scratch (device globals; zero-init bss) -------------------
__device__ bf16 g_Xhi [BATCH * DDIM * NSEQ], g_Xlo [BATCH * DDIM * NSEQ];   // (b,d,n)
__device__ bf16 g_XThi[BATCH * NSEQ * DDIM], g_XTlo[BATCH * NSEQ * DDIM];   // (b,i,d)
__device__ bf16 g_WQhi[KDIM * DDIM], g_WQlo[KDIM * DDIM];                   // (k,d)
__device__ bf16 g_WKhi[KDIM * DDIM], g_WKlo[KDIM * DDIM];
__device__ bf16 g_WOThi[DDIM * KDIM], g_WOTlo[DDIM * KDIM];                 // (d,k)
__device__ bf16 g_WVThi[DDIM * KDIM], g_WVTlo[DDIM * KDIM];                 // (e,k)
__device__ bf16 g_qhi [BATCH * NSEQ * KDIM], g_qlo [BATCH * NSEQ * KDIM];   // (b,i,k)
__device__ bf16 g_khi [BATCH * NSEQ * KDIM], g_klo [BATCH * NSEQ * KDIM];   // (b,j,k)
__device__ bf16 g_Mhi [DDIM * DDIM], g_Mlo [DDIM * DDIM];                   // (d,e)
__device__ float g_L  [BATCH * NSEQ * NSEQ];                                // logits fp32
__device__ bf16 g_Ahi [BATCH * NSEQ * NSEQ], g_Alo [BATCH * NSEQ * NSEQ];   // softmax out
__device__ bf16 g_cthi[BATCH * NSEQ * DDIM], g_ctlo[BATCH * NSEQ * DDIM];   // (b,i,e)

// ---------------- helpers ----------------------------------------------------
__device__ __forceinline__ uint32_t smem_u32(const void* p) {
    uint32_t a;
    asm("{ .reg .u64 t; cvta.to.shared.u64 t, %1; cvt.u32.u64 %0, t; }" : "=r"(a) : "l"(p));
    return a;
}
__device__ __forceinline__ void ldsm4(uint32_t* r, uint32_t addr) {
    asm volatile("ldmatrix.sync.aligned.m8n8.x4.shared.b16 {%0,%1,%2,%3}, [%4];"
                 : "=r"(r[0]), "=r"(r[1]), "=r"(r[2]), "=r"(r[3]) : "r"(addr));
}
__device__ __forceinline__ void mma16816(float* d, const uint32_t* a, const uint32_t* b) {
    asm volatile(
        "mma.sync.aligned.m16n8k16.row.col.f32.bf16.bf16.f32 "
        "{%0,%1,%2,%3}, {%4,%5,%6,%7}, {%8,%9}, {%0,%1,%2,%3};"
        : "+f"(d[0]), "+f"(d[1]), "+f"(d[2]), "+f"(d[3])
        : "r"(a[0]), "r"(a[1]), "r"(a[2]), "r"(a[3]), "r"(b[0]), "r"(b[1]));
}
__device__ __forceinline__ void cpasync16(uint32_t dst, const void* src) {
    asm volatile("cp.async.cg.shared.global [%0], [%1], 16;" :: "r"(dst), "l"(src));
}
__device__ __forceinline__ void cp_commit() { asm volatile("cp.async.commit_group;"); }
__device__ __forceinline__ void cp_wait1()  { asm volatile("cp.async.wait_group 1;"); }

__device__ __forceinline__ uint32_t pack_hi(float a, float b) {
    bf16 h0 = __float2bfloat16(a), h1 = __float2bfloat16(b);
    return (uint32_t)__bfloat16_as_ushort(h0) | ((uint32_t)__bfloat16_as_ushort(h1) << 16);
}
__device__ __forceinline__ uint32_t pack_lo(float a, float b) {
    bf16 h0 = __float2bfloat16(a), h1 = __float2bfloat16(b);
    float l0 = a - __bfloat162float(h0), l1 = b - __bfloat162float(h1);
    return (uint32_t)__bfloat16_as_ushort(__float2bfloat16(l0)) |
           ((uint32_t)__bfloat16_as_ushort(__float2bfloat16(l1)) << 16);
}

// ---------------- convert fp32 -> bf16 hi/lo --------------------------------
__global__ void convert_hl(const float* __restrict__ in, bf16* __restrict__ hi,
                           bf16* __restrict__ lo, long long n) {
    long long i = ((long long)blockIdx.x * blockDim.x + threadIdx.x) * 4;
    if (i >= n) return;
    float4 v = *(const float4*)(in + i);
    *(uint2*)(hi + i) = make_uint2(pack_hi(v.x, v.y), pack_hi(v.z, v.w));
    *(uint2*)(lo + i) = make_uint2(pack_lo(v.x, v.y), pack_lo(v.z, v.w));
}

// ---------------- transpose fp32 -> bf16 hi/lo: out[c][r] = in[r][c] --------
__global__ void transpose_hl(const float* __restrict__ in, bf16* __restrict__ hi,
                             bf16* __restrict__ lo, int rows, int cols,
                             long long sIn, long long sOut) {
    __shared__ float tile[32][33];
    const float* I = in + (long long)blockIdx.z * sIn;
    int r0 = blockIdx.y * 32, c0 = blockIdx.x * 32;
    int x = threadIdx.x, y = threadIdx.y;
#pragma unroll
    for (int j = y; j < 32; j += 8)
        tile[j][x] = I[(long long)(r0 + j) * cols + c0 + x];
    __syncthreads();
    long long zo = (long long)blockIdx.z * sOut;
#pragma unroll
    for (int j = y; j < 32; j += 8) {
        float v = tile[x][j];
        long long o = zo + (long long)(c0 + j) * rows + r0 + x;
        bf16 h = __float2bfloat16(v);
        hi[o] = h;
        lo[o] = __float2bfloat16(v - __bfloat162float(h));
    }
}

// ---------------- bf16 hi/lo HMMA NT GEMM -----------------------------------
// C[m][n] = sum_k A[m][k]*B[n][k], A/B given as hi/lo bf16 (ld=Kk).
// Output: fp32 (+res) if Cf != null, else bf16 hi/lo pair.
// causal: skip n-tiles above the diagonal band (logits).
// kcap:   A rows are causal-zero beyond k >= m0+TM (ctx GEMM) -> cap k-loop.
#define TM 128
#define TN 128
#define KC 32
#define TILE_B 8192            // 128 rows x 64B (swizzled)
#define STAGE_B (4 * TILE_B)   // Ahi, Alo, Bhi, Blo
#define STAGES 3
#define GSMEM (STAGES * STAGE_B)

__global__ void __launch_bounds__(256, 2)
hgemm(const bf16* __restrict__ Ahi_, const bf16* __restrict__ Alo_,
      const bf16* __restrict__ Bhi_, const bf16* __restrict__ Blo_,
      float* __restrict__ Cf, bf16* __restrict__ Chi, bf16* __restrict__ Clo,
      const float* __restrict__ Res,
      int M, int N, int Kk,
      long long sA, long long sB, long long sC, long long sRes,
      int causal, int kcap) {
    // heavy blocks first when work varies with m0
    int by = (causal || kcap) ? (gridDim.y - 1 - blockIdx.y) : blockIdx.y;
    int m0 = by * TM;
    int n0 = blockIdx.x * TN;
    if (causal && n0 > m0 + TM - 1) return;

    extern __shared__ char sm[];
    uint32_t sb = smem_u32(sm);
    int tid = threadIdx.x, lane = tid & 31, wid = tid >> 5;
    int wm = wid & 1, wn = wid >> 1;
    long long z = blockIdx.z;

    // cp.async mapping: thread covers one row, two adjacent 16B segs, x4 tiles
    int row = tid >> 1, seg0 = (tid & 1) * 2;
    int ssw = (row >> 1) & 3;
    uint32_t so0 = (uint32_t)(row * 64 + ((seg0 ^ ssw) << 4));
    uint32_t so1 = (uint32_t)(row * 64 + (((seg0 + 1) ^ ssw) << 4));
    const bf16* pAhi = Ahi_ + z * sA + (long long)(m0 + row) * Kk + seg0 * 8;
    const bf16* pAlo = Alo_ + z * sA + (long long)(m0 + row) * Kk + seg0 * 8;
    const bf16* pBhi = Bhi_ + z * sB + (long long)(n0 + row) * Kk + seg0 * 8;
    const bf16* pBlo = Blo_ + z * sB + (long long)(n0 + row) * Kk + seg0 * 8;

    // ldmatrix addressing (64B rows, 16B-chunk XOR swizzle)
    int ra = wm * 64 + (lane & 15);
    int abit = lane >> 4;
    uint32_t aRow = (uint32_t)ra * 64;
    int swA = (ra >> 1) & 3;
    uint32_t colA[2] = { (uint32_t)(((0 + abit) ^ swA) << 4),
                         (uint32_t)(((2 + abit) ^ swA) << 4) };
    int rb = wn * 32 + ((lane >> 4) << 3) + (lane & 7);
    int bbit = (lane >> 3) & 1;
    uint32_t bRow = (uint32_t)rb * 64;
    int swB = (rb >> 1) & 3;
    uint32_t colB[2] = { (uint32_t)(((0 + bbit) ^ swB) << 4),
                         (uint32_t)(((2 + bbit) ^ swB) << 4) };

    float acc[4][4][4];
#pragma unroll
    for (int mt = 0; mt < 4; ++mt)
#pragma unroll
        for (int nt = 0; nt < 4; ++nt)
#pragma unroll
            for (int r = 0; r < 4; ++r) acc[mt][nt][r] = 0.f;

    int KkE = kcap ? (m0 + TM < Kk ? m0 + TM : Kk) : Kk;
    const int nc = KkE / KC;

    // prologue: stage chunks 0,1
#pragma unroll
    for (int s = 0; s < STAGES - 1; ++s) {
        long long off = (long long)s * KC;
        uint32_t d = sb + s * STAGE_B;
        cpasync16(d + 0 * TILE_B + so0, pAhi + off);
        cpasync16(d + 0 * TILE_B + so1, pAhi + off + 8);
        cpasync16(d + 1 * TILE_B + so0, pAlo + off);
        cpasync16(d + 1 * TILE_B + so1, pAlo + off + 8);
        cpasync16(d + 2 * TILE_B + so0, pBhi + off);
        cpasync16(d + 2 * TILE_B + so1, pBhi + off + 8);
        cpasync16(d + 3 * TILE_B + so0, pBlo + off);
        cpasync16(d + 3 * TILE_B + so1, pBlo + off + 8);
        cp_commit();
    }

    for (int c = 0; c < nc; ++c) {
        cp_wait1();
        __syncthreads();
        if (c + 2 < nc) {
            int st = (c + 2) % STAGES;
            long long off = (long long)(c + 2) * KC;
            uint32_t d = sb + st * STAGE_B;
            cpasync16(d + 0 * TILE_B + so0, pAhi + off);
            cpasync16(d + 0 * TILE_B + so1, pAhi + off + 8);
            cpasync16(d + 1 * TILE_B + so0, pAlo + off);
            cpasync16(d + 1 * TILE_B + so1, pAlo + off + 8);
            cpasync16(d + 2 * TILE_B + so0, pBhi + off);
            cpasync16(d + 2 * TILE_B + so1, pBhi + off + 8);
            cpasync16(d + 3 * TILE_B + so0, pBlo + off);
            cpasync16(d + 3 * TILE_B + so1, pBlo + off + 8);
            cp_commit();
        } else {
            cp_commit();
        }

        uint32_t bA = sb + (c % STAGES) * STAGE_B;
        uint32_t bAhi = bA, bAlo = bA + TILE_B, bBhi = bA + 2 * TILE_B, bBlo = bA + 3 * TILE_B;

#pragma unroll
        for (int kk2 = 0; kk2 < 2; ++kk2) {
            uint32_t ah[4][4], bh[4][2];
#pragma unroll
            for (int mt = 0; mt < 4; ++mt)
                ldsm4(ah[mt], bAhi + aRow + mt * 1024 + colA[kk2]);
#pragma unroll
            for (int jp = 0; jp < 2; ++jp) {
                uint32_t r[4];
                ldsm4(r, bBhi + bRow + jp * 1024 + colB[kk2]);
                bh[2 * jp][0] = r[0]; bh[2 * jp][1] = r[1];
                bh[2 * jp + 1][0] = r[2]; bh[2 * jp + 1][1] = r[3];
            }
#pragma unroll
            for (int mt = 0; mt < 4; ++mt)
#pragma unroll
                for (int nt = 0; nt < 4; ++nt)
                    mma16816(acc[mt][nt], ah[mt], bh[nt]);

            uint32_t bl[4][2];
#pragma unroll
            for (int jp = 0; jp < 2; ++jp) {
                uint32_t r[4];
                ldsm4(r, bBlo + bRow + jp * 1024 + colB[kk2]);
                bl[2 * jp][0] = r[0]; bl[2 * jp][1] = r[1];
                bl[2 * jp + 1][0] = r[2]; bl[2 * jp + 1][1] = r[3];
            }
#pragma unroll
            for (int mt = 0; mt < 4; ++mt)
#pragma unroll
                for (int nt = 0; nt < 4; ++nt)
                    mma16816(acc[mt][nt], ah[mt], bl[nt]);

            uint32_t al[4][4];
#pragma unroll
            for (int mt = 0; mt < 4; ++mt)
                ldsm4(al[mt], bAlo + aRow + mt * 1024 + colA[kk2]);
#pragma unroll
            for (int mt = 0; mt < 4; ++mt)
#pragma unroll
                for (int nt = 0; nt < 4; ++nt)
                    mma16816(acc[mt][nt], al[mt], bh[nt]);
        }
    }

    // epilogue
    int er = lane >> 2, ec = (lane & 3) * 2;
    if (Cf) {
        float* Cb = Cf + z * sC;
        const float* Rb = Res ? Res + z * sRes : nullptr;
#pragma unroll
        for (int mt = 0; mt < 4; ++mt) {
#pragma unroll
            for (int nt = 0; nt < 4; ++nt) {
                long long r0 = (long long)(m0 + wm * 64 + mt * 16 + er);
                int col = n0 + wn * 32 + nt * 8 + ec;
                float2 v0 = make_float2(acc[mt][nt][0], acc[mt][nt][1]);
                float2 v1 = make_float2(acc[mt][nt][2], acc[mt][nt][3]);
                if (Rb) {
                    float2 q0 = *(const float2*)(Rb + r0 * N + col);
                    float2 q1 = *(const float2*)(Rb + (r0 + 8) * N + col);
                    v0.x += q0.x; v0.y += q0.y; v1.x += q1.x; v1.y += q1.y;
                }
                *(float2*)(Cb + r0 * N + col)       = v0;
                *(float2*)(Cb + (r0 + 8) * N + col) = v1;
            }
        }
    } else {
        bf16* Hb = Chi + z * sC;
        bf16* Lb = Clo + z * sC;
#pragma unroll
        for (int mt = 0; mt < 4; ++mt) {
#pragma unroll
            for (int nt = 0; nt < 4; ++nt) {
                long long r0 = (long long)(m0 + wm * 64 + mt * 16 + er);
                int col = n0 + wn * 32 + nt * 8 + ec;
#pragma unroll
                for (int h = 0; h < 2; ++h) {
                    float v0 = acc[mt][nt][2 * h], v1 = acc[mt][nt][2 * h + 1];
                    long long o = (r0 + 8 * h) * N + col;
                    *(uint32_t*)(Hb + o) = pack_hi(v0, v1);
                    *(uint32_t*)(Lb + o) = pack_lo(v0, v1);
                }
            }
        }
    }
}

// ---------------- row softmax: L fp32 -> A bf16 hi/lo, causal ---------------
__global__ void softmax_rows(const float* __restrict__ L, bf16* __restrict__ Ahi,
                             bf16* __restrict__ Alo, int Nn) {
    int b = blockIdx.y, i = blockIdx.x;
    const float* row = L + ((long long)b * Nn + i) * Nn;
    bf16* ah = Ahi + ((long long)b * Nn + i) * Nn;
    bf16* al = Alo + ((long long)b * Nn + i) * Nn;
    int nv = i + 1;
    int t = threadIdx.x;
    __shared__ float red[256];

    float m = -1e30f;
    for (int j = t; j < nv; j += 256) m = fmaxf(m, row[j]);
    red[t] = m; __syncthreads();
    for (int s = 128; s > 0; s >>= 1) {
        if (t < s) red[t] = fmaxf(red[t], red[t + s]);
        __syncthreads();
    }
    m = red[0]; __syncthreads();

    float ssum = 0.f;
    for (int j = t; j < nv; j += 256) ssum += __expf(row[j] - m);
    red[t] = ssum; __syncthreads();
    for (int s = 128; s > 0; s >>= 1) {
        if (t < s) red[t] += red[t + s];
        __syncthreads();
    }
    float inv = 1.f / red[0];

    for (int j = t; j < nv; j += 256) {
        float v = __expf(row[j] - m) * inv;
        bf16 h = __float2bfloat16(v);
        ah[j] = h;
        al[j] = __float2bfloat16(v - __bfloat162float(h));
    }
    bf16 zz = __float2bfloat16(0.f);
    for (int j = nv + t; j < Nn; j += 256) { ah[j] = zz; al[j] = zz; }
}

// ---------------- launch ----------------------------------------------------
extern "C" void kernel_launch(void* const* d_in, const int* in_sizes, int n_in,
                              void* d_out, int out_size) {
    const float* X   = (const float*)d_in[0];
    const float* W_Q = (const float*)d_in[1];
    const float* W_K = (const float*)d_in[2];
    const float* W_V = (const float*)d_in[3];
    const float* W_O = (const float*)d_in[4];
    float* out = (float*)d_out;

    bf16 *Xhi, *Xlo, *XThi, *XTlo, *WQhi, *WQlo, *WKhi, *WKlo;
    bf16 *WOThi, *WOTlo, *WVThi, *WVTlo, *qhi, *qlo, *khi, *klo;
    bf16 *Mhi, *Mlo, *Ahi, *Alo, *cthi, *ctlo;
    float* L;
    cudaGetSymbolAddress((void**)&Xhi, g_Xhi);   cudaGetSymbolAddress((void**)&Xlo, g_Xlo);
    cudaGetSymbolAddress((void**)&XThi, g_XThi); cudaGetSymbolAddress((void**)&XTlo, g_XTlo);
    cudaGetSymbolAddress((void**)&WQhi, g_WQhi); cudaGetSymbolAddress((void**)&WQlo, g_WQlo);
    cudaGetSymbolAddress((void**)&WKhi, g_WKhi); cudaGetSymbolAddress((void**)&WKlo, g_WKlo);
    cudaGetSymbolAddress((void**)&WOThi, g_WOThi); cudaGetSymbolAddress((void**)&WOTlo, g_WOTlo);
    cudaGetSymbolAddress((void**)&WVThi, g_WVThi); cudaGetSymbolAddress((void**)&WVTlo, g_WVTlo);
    cudaGetSymbolAddress((void**)&qhi, g_qhi);   cudaGetSymbolAddress((void**)&qlo, g_qlo);
    cudaGetSymbolAddress((void**)&khi, g_khi);   cudaGetSymbolAddress((void**)&klo, g_klo);
    cudaGetSymbolAddress((void**)&Mhi, g_Mhi);   cudaGetSymbolAddress((void**)&Mlo, g_Mlo);
    cudaGetSymbolAddress((void**)&Ahi, g_Ahi);   cudaGetSymbolAddress((void**)&Alo, g_Alo);
    cudaGetSymbolAddress((void**)&cthi, g_cthi); cudaGetSymbolAddress((void**)&ctlo, g_ctlo);
    cudaGetSymbolAddress((void**)&L, g_L);

    cudaFuncSetAttribute(hgemm, cudaFuncAttributeMaxDynamicSharedMemorySize, GSMEM);

    const long long sX  = (long long)DDIM * NSEQ;
    const long long sXT = (long long)NSEQ * DDIM;
    const long long sQ  = (long long)NSEQ * KDIM;
    const long long sL  = (long long)NSEQ * NSEQ;

    // input conversions
    convert_hl<<<(int)((long long)BATCH * sX / 4 / 256), 256>>>(X, Xhi, Xlo, (long long)BATCH * sX);
    convert_hl<<<(KDIM * DDIM / 4) / 256, 256>>>(W_Q, WQhi, WQlo, KDIM * DDIM);
    convert_hl<<<(KDIM * DDIM / 4) / 256, 256>>>(W_K, WKhi, WKlo, KDIM * DDIM);
    dim3 tb(32, 8);
    transpose_hl<<<dim3(NSEQ / 32, DDIM / 32, BATCH), tb>>>(X, XThi, XTlo, DDIM, NSEQ, sX, sXT);
    transpose_hl<<<dim3(DDIM / 32, KDIM / 32, 1), tb>>>(W_O, WOThi, WOTlo, KDIM, DDIM, 0, 0);
    transpose_hl<<<dim3(DDIM / 32, KDIM / 32, 1), tb>>>(W_V, WVThi, WVTlo, KDIM, DDIM, 0, 0);

    // q[i][k] = sum_d XT[i][d] * W_Q[k][d]   (bf16 out)
    hgemm<<<dim3(KDIM / TN, NSEQ / TM, BATCH), 256, GSMEM>>>(
        XThi, XTlo, WQhi, WQlo, nullptr, qhi, qlo, nullptr,
        NSEQ, KDIM, DDIM, sXT, 0, sQ, 0, 0, 0);
    hgemm<<<dim3(KDIM / TN, NSEQ / TM, BATCH), 256, GSMEM>>>(
        XThi, XTlo, WKhi, WKlo, nullptr, khi, klo, nullptr,
        NSEQ, KDIM, DDIM, sXT, 0, sQ, 0, 0, 0);

    // M'[d][e] = sum_k WOT[d][k] * WVT[e][k]   (bf16 out)
    hgemm<<<dim3(DDIM / TN, DDIM / TM, 1), 256, GSMEM>>>(
        WOThi, WOTlo, WVThi, WVTlo, nullptr, Mhi, Mlo, nullptr,
        DDIM, DDIM, KDIM, 0, 0, 0, 0, 0, 0);

    // L[i][j] = sum_k q[i][k] * kk[j][k]  (fp32 out, causal tile skip)
    hgemm<<<dim3(NSEQ / TN, NSEQ / TM, BATCH), 256, GSMEM>>>(
        qhi, qlo, khi, klo, L, nullptr, nullptr, nullptr,
        NSEQ, NSEQ, KDIM, sQ, sQ, sL, 0, 1, 0);

    softmax_rows<<<dim3(NSEQ, BATCH), 256>>>(L, Ahi, Alo, NSEQ);

    // ctxT[i][e] = sum_t A[i][t] * X[e][t]   (bf16 out; k-loop capped at m0+TM)
    hgemm<<<dim3(DDIM / TN, NSEQ / TM, BATCH), 256, GSMEM>>>(
        Ahi, Alo, Xhi, Xlo, nullptr, cthi, ctlo, nullptr,
        NSEQ, DDIM, NSEQ, sL, sX, sXT, 0, 0, 1);

    // out[d][i] = X[d][i] + sum_e M'[d][e] * ctxT[i][e]   (fp32 out + residual)
    hgemm<<<dim3(NSEQ / TN, DDIM / TM, BATCH), 256, GSMEM>>>(
        Mhi, Mlo, cthi, ctlo, out, nullptr, nullptr, X,
        DDIM, NSEQ, DDIM, 0, sXT, sX, sX, 0, 0);
}

// round 8
// speedup vs baseline: 2.8145x; 1.0923x over previous
#include <cuda_runtime.h>
#include <cuda_bf16.h>
#include <cstdint>

#define BATCH 4
#define DDIM  1024
#define NSEQ  2048
#define KDIM  1024

typedef __nv_bfloat16 bf16;

// ---------------- scratch (device globals; zero-init bss) -------------------
__device__ bf16 g_Xhi [BATCH * DDIM * NSEQ], g_Xlo [BATCH * DDIM * NSEQ];   // (b,d,n)
__device__ bf16 g_XThi[BATCH * NSEQ * DDIM], g_XTlo[BATCH * NSEQ * DDIM];   // (b,i,d)
__device__ bf16 g_WQhi[KDIM * DDIM], g_WQlo[KDIM * DDIM];                   // (k,d)
__device__ bf16 g_WKhi[KDIM * DDIM], g_WKlo[KDIM * DDIM];
__device__ bf16 g_WOThi[DDIM * KDIM], g_WOTlo[DDIM * KDIM];                 // (d,k)
__device__ bf16 g_WVThi[DDIM * KDIM], g_WVTlo[DDIM * KDIM];                 // (e,k)
__device__ bf16 g_qhi [BATCH * NSEQ * KDIM], g_qlo [BATCH * NSEQ * KDIM];   // (b,i,k)
__device__ bf16 g_khi [BATCH * NSEQ * KDIM], g_klo [BATCH * NSEQ * KDIM];   // (b,j,k)
__device__ bf16 g_Mhi [DDIM * DDIM], g_Mlo [DDIM * DDIM];                   // (d,e)
__device__ float g_L  [BATCH * NSEQ * NSEQ];                                // logits fp32
__device__ bf16 g_Ahi [BATCH * NSEQ * NSEQ], g_Alo [BATCH * NSEQ * NSEQ];   // softmax out
__device__ bf16 g_cthi[BATCH * NSEQ * DDIM], g_ctlo[BATCH * NSEQ * DDIM];   // (b,i,e)

// ---------------- helpers ----------------------------------------------------
__device__ __forceinline__ uint32_t smem_u32(const void* p) {
    uint32_t a;
    asm("{ .reg .u64 t; cvta.to.shared.u64 t, %1; cvt.u32.u64 %0, t; }" : "=r"(a) : "l"(p));
    return a;
}
__device__ __forceinline__ void ldsm4(uint32_t* r, uint32_t addr) {
    asm volatile("ldmatrix.sync.aligned.m8n8.x4.shared.b16 {%0,%1,%2,%3}, [%4];"
                 : "=r"(r[0]), "=r"(r[1]), "=r"(r[2]), "=r"(r[3]) : "r"(addr));
}
__device__ __forceinline__ void mma16816(float* d, const uint32_t* a, const uint32_t* b) {
    asm volatile(
        "mma.sync.aligned.m16n8k16.row.col.f32.bf16.bf16.f32 "
        "{%0,%1,%2,%3}, {%4,%5,%6,%7}, {%8,%9}, {%0,%1,%2,%3};"
        : "+f"(d[0]), "+f"(d[1]), "+f"(d[2]), "+f"(d[3])
        : "r"(a[0]), "r"(a[1]), "r"(a[2]), "r"(a[3]), "r"(b[0]), "r"(b[1]));
}
__device__ __forceinline__ void cpasync16(uint32_t dst, const void* src) {
    asm volatile("cp.async.cg.shared.global [%0], [%1], 16;" :: "r"(dst), "l"(src));
}
__device__ __forceinline__ void cp_commit() { asm volatile("cp.async.commit_group;"); }
__device__ __forceinline__ void cp_wait1()  { asm volatile("cp.async.wait_group 1;"); }

__device__ __forceinline__ uint32_t pack_hi(float a, float b) {
    bf16 h0 = __float2bfloat16(a), h1 = __float2bfloat16(b);
    return (uint32_t)__bfloat16_as_ushort(h0) | ((uint32_t)__bfloat16_as_ushort(h1) << 16);
}
__device__ __forceinline__ uint32_t pack_lo(float a, float b) {
    bf16 h0 = __float2bfloat16(a), h1 = __float2bfloat16(b);
    float l0 = a - __bfloat162float(h0), l1 = b - __bfloat162float(h1);
    return (uint32_t)__bfloat16_as_ushort(__float2bfloat16(l0)) |
           ((uint32_t)__bfloat16_as_ushort(__float2bfloat16(l1)) << 16);
}

// ---------------- convert fp32 -> bf16 hi/lo --------------------------------
__global__ void convert_hl(const float* __restrict__ in, bf16* __restrict__ hi,
                           bf16* __restrict__ lo, long long n) {
    long long i = ((long long)blockIdx.x * blockDim.x + threadIdx.x) * 4;
    if (i >= n) return;
    float4 v = *(const float4*)(in + i);
    *(uint2*)(hi + i) = make_uint2(pack_hi(v.x, v.y), pack_hi(v.z, v.w));
    *(uint2*)(lo + i) = make_uint2(pack_lo(v.x, v.y), pack_lo(v.z, v.w));
}

// ---------------- transpose fp32 -> bf16 hi/lo: out[c][r] = in[r][c] --------
__global__ void transpose_hl(const float* __restrict__ in, bf16* __restrict__ hi,
                             bf16* __restrict__ lo, int rows, int cols,
                             long long sIn, long long sOut) {
    __shared__ float tile[32][33];
    const float* I = in + (long long)blockIdx.z * sIn;
    int r0 = blockIdx.y * 32, c0 = blockIdx.x * 32;
    int x = threadIdx.x, y = threadIdx.y;
#pragma unroll
    for (int j = y; j < 32; j += 8)
        tile[j][x] = I[(long long)(r0 + j) * cols + c0 + x];
    __syncthreads();
    long long zo = (long long)blockIdx.z * sOut;
#pragma unroll
    for (int j = y; j < 32; j += 8) {
        float v = tile[x][j];
        long long o = zo + (long long)(c0 + j) * rows + r0 + x;
        bf16 h = __float2bfloat16(v);
        hi[o] = h;
        lo[o] = __float2bfloat16(v - __bfloat162float(h));
    }
}

// ---------------- fused X: convert + transpose in one pass ------------------
// in (b,D,N) -> hi/lo (b,D,N) and thi/tlo (b,N,D)
__global__ void convtrans_X(const float* __restrict__ in,
                            bf16* __restrict__ hi, bf16* __restrict__ lo,
                            bf16* __restrict__ thi, bf16* __restrict__ tlo) {
    __shared__ float tile[32][33];
    long long zb = (long long)blockIdx.z * DDIM * NSEQ;
    int r0 = blockIdx.y * 32, c0 = blockIdx.x * 32;   // r0: d, c0: n
    int x = threadIdx.x, y = threadIdx.y;
#pragma unroll
    for (int j = y; j < 32; j += 8) {
        long long o = zb + (long long)(r0 + j) * NSEQ + c0 + x;
        float v = in[o];
        tile[j][x] = v;
        bf16 h = __float2bfloat16(v);
        hi[o] = h;
        lo[o] = __float2bfloat16(v - __bfloat162float(h));
    }
    __syncthreads();
#pragma unroll
    for (int j = y; j < 32; j += 8) {
        float v = tile[x][j];
        long long o = zb + (long long)(c0 + j) * DDIM + r0 + x;
        bf16 h = __float2bfloat16(v);
        thi[o] = h;
        tlo[o] = __float2bfloat16(v - __bfloat162float(h));
    }
}

// ---------------- bf16 hi/lo HMMA NT GEMM -----------------------------------
#define TM 128
#define TN 128
#define KC 32
#define TILE_B 8192            // 128 rows x 64B (swizzled)
#define STAGE_B (4 * TILE_B)   // Ahi, Alo, Bhi, Blo
#define STAGES 3
#define GSMEM (STAGES * STAGE_B)

__global__ void __launch_bounds__(256, 2)
hgemm(const bf16* __restrict__ Ahi_, const bf16* __restrict__ Alo_,
      const bf16* __restrict__ Bhi_, const bf16* __restrict__ Blo_,
      float* __restrict__ Cf, bf16* __restrict__ Chi, bf16* __restrict__ Clo,
      const float* __restrict__ Res,
      int M, int N, int Kk,
      long long sA, long long sB, long long sC, long long sRes,
      int causal, int kcap) {
    int by = (causal || kcap) ? (gridDim.y - 1 - blockIdx.y) : blockIdx.y;
    int m0 = by * TM;
    int n0 = blockIdx.x * TN;
    if (causal && n0 > m0 + TM - 1) return;

    extern __shared__ char sm[];
    uint32_t sb = smem_u32(sm);
    int tid = threadIdx.x, lane = tid & 31, wid = tid >> 5;
    int wm = wid & 1, wn = wid >> 1;
    long long z = blockIdx.z;

    // cp.async mapping: thread covers one row, two adjacent 16B segs, x4 tiles
    int row = tid >> 1, seg0 = (tid & 1) * 2;
    int ssw = (row >> 1) & 3;
    uint32_t so0 = (uint32_t)(row * 64 + ((seg0 ^ ssw) << 4));
    uint32_t so1 = (uint32_t)(row * 64 + (((seg0 + 1) ^ ssw) << 4));
    const bf16* pAhi = Ahi_ + z * sA + (long long)(m0 + row) * Kk + seg0 * 8;
    const bf16* pAlo = Alo_ + z * sA + (long long)(m0 + row) * Kk + seg0 * 8;
    const bf16* pBhi = Bhi_ + z * sB + (long long)(n0 + row) * Kk + seg0 * 8;
    const bf16* pBlo = Blo_ + z * sB + (long long)(n0 + row) * Kk + seg0 * 8;

    // ldmatrix addressing (64B rows, 16B-chunk XOR swizzle)
    int ra = wm * 64 + (lane & 15);
    int abit = lane >> 4;
    uint32_t aRow = (uint32_t)ra * 64;
    int swA = (ra >> 1) & 3;
    uint32_t colA[2] = { (uint32_t)(((0 + abit) ^ swA) << 4),
                         (uint32_t)(((2 + abit) ^ swA) << 4) };
    int rb = wn * 32 + ((lane >> 4) << 3) + (lane & 7);
    int bbit = (lane >> 3) & 1;
    uint32_t bRow = (uint32_t)rb * 64;
    int swB = (rb >> 1) & 3;
    uint32_t colB[2] = { (uint32_t)(((0 + bbit) ^ swB) << 4),
                         (uint32_t)(((2 + bbit) ^ swB) << 4) };

    float acc[4][4][4];
#pragma unroll
    for (int mt = 0; mt < 4; ++mt)
#pragma unroll
        for (int nt = 0; nt < 4; ++nt)
#pragma unroll
            for (int r = 0; r < 4; ++r) acc[mt][nt][r] = 0.f;

    int KkE = kcap ? (m0 + TM < Kk ? m0 + TM : Kk) : Kk;
    const int nc = KkE / KC;

#pragma unroll
    for (int s = 0; s < STAGES - 1; ++s) {
        long long off = (long long)s * KC;
        uint32_t d = sb + s * STAGE_B;
        cpasync16(d + 0 * TILE_B + so0, pAhi + off);
        cpasync16(d + 0 * TILE_B + so1, pAhi + off + 8);
        cpasync16(d + 1 * TILE_B + so0, pAlo + off);
        cpasync16(d + 1 * TILE_B + so1, pAlo + off + 8);
        cpasync16(d + 2 * TILE_B + so0, pBhi + off);
        cpasync16(d + 2 * TILE_B + so1, pBhi + off + 8);
        cpasync16(d + 3 * TILE_B + so0, pBlo + off);
        cpasync16(d + 3 * TILE_B + so1, pBlo + off + 8);
        cp_commit();
    }

    for (int c = 0; c < nc; ++c) {
        cp_wait1();
        __syncthreads();
        if (c + 2 < nc) {
            int st = (c + 2) % STAGES;
            long long off = (long long)(c + 2) * KC;
            uint32_t d = sb + st * STAGE_B;
            cpasync16(d + 0 * TILE_B + so0, pAhi + off);
            cpasync16(d + 0 * TILE_B + so1, pAhi + off + 8);
            cpasync16(d + 1 * TILE_B + so0, pAlo + off);
            cpasync16(d + 1 * TILE_B + so1, pAlo + off + 8);
            cpasync16(d + 2 * TILE_B + so0, pBhi + off);
            cpasync16(d + 2 * TILE_B + so1, pBhi + off + 8);
            cpasync16(d + 3 * TILE_B + so0, pBlo + off);
            cpasync16(d + 3 * TILE_B + so1, pBlo + off + 8);
            cp_commit();
        } else {
            cp_commit();
        }

        uint32_t bA = sb + (c % STAGES) * STAGE_B;
        uint32_t bAhi = bA, bAlo = bA + TILE_B, bBhi = bA + 2 * TILE_B, bBlo = bA + 3 * TILE_B;

#pragma unroll
        for (int kk2 = 0; kk2 < 2; ++kk2) {
            // front-load A-hi, B-hi, B-lo so the first MMA group covers B-lo latency
            uint32_t ah[4][4], bh[4][2], bl[4][2];
#pragma unroll
            for (int mt = 0; mt < 4; ++mt)
                ldsm4(ah[mt], bAhi + aRow + mt * 1024 + colA[kk2]);
#pragma unroll
            for (int jp = 0; jp < 2; ++jp) {
                uint32_t r[4];
                ldsm4(r, bBhi + bRow + jp * 1024 + colB[kk2]);
                bh[2 * jp][0] = r[0]; bh[2 * jp][1] = r[1];
                bh[2 * jp + 1][0] = r[2]; bh[2 * jp + 1][1] = r[3];
            }
#pragma unroll
            for (int jp = 0; jp < 2; ++jp) {
                uint32_t r[4];
                ldsm4(r, bBlo + bRow + jp * 1024 + colB[kk2]);
                bl[2 * jp][0] = r[0]; bl[2 * jp][1] = r[1];
                bl[2 * jp + 1][0] = r[2]; bl[2 * jp + 1][1] = r[3];
            }
#pragma unroll
            for (int mt = 0; mt < 4; ++mt)
#pragma unroll
                for (int nt = 0; nt < 4; ++nt)
                    mma16816(acc[mt][nt], ah[mt], bh[nt]);

            // A-lo loads overlap the ah*bl MMA group
            uint32_t al[4][4];
#pragma unroll
            for (int mt = 0; mt < 4; ++mt)
                ldsm4(al[mt], bAlo + aRow + mt * 1024 + colA[kk2]);
#pragma unroll
            for (int mt = 0; mt < 4; ++mt)
#pragma unroll
                for (int nt = 0; nt < 4; ++nt)
                    mma16816(acc[mt][nt], ah[mt], bl[nt]);
#pragma unroll
            for (int mt = 0; mt < 4; ++mt)
#pragma unroll
                for (int nt = 0; nt < 4; ++nt)
                    mma16816(acc[mt][nt], al[mt], bh[nt]);
        }
    }

    // epilogue
    int er = lane >> 2, ec = (lane & 3) * 2;
    if (Cf) {
        float* Cb = Cf + z * sC;
        const float* Rb = Res ? Res + z * sRes : nullptr;
#pragma unroll
        for (int mt = 0; mt < 4; ++mt) {
#pragma unroll
            for (int nt = 0; nt < 4; ++nt) {
                long long r0 = (long long)(m0 + wm * 64 + mt * 16 + er);
                int col = n0 + wn * 32 + nt * 8 + ec;
                float2 v0 = make_float2(acc[mt][nt][0], acc[mt][nt][1]);
                float2 v1 = make_float2(acc[mt][nt][2], acc[mt][nt][3]);
                if (Rb) {
                    float2 q0 = *(const float2*)(Rb + r0 * N + col);
                    float2 q1 = *(const float2*)(Rb + (r0 + 8) * N + col);
                    v0.x += q0.x; v0.y += q0.y; v1.x += q1.x; v1.y += q1.y;
                }
                *(float2*)(Cb + r0 * N + col)       = v0;
                *(float2*)(Cb + (r0 + 8) * N + col) = v1;
            }
        }
    } else {
        bf16* Hb = Chi + z * sC;
        bf16* Lb = Clo + z * sC;
#pragma unroll
        for (int mt = 0; mt < 4; ++mt) {
#pragma unroll
            for (int nt = 0; nt < 4; ++nt) {
                long long r0 = (long long)(m0 + wm * 64 + mt * 16 + er);
                int col = n0 + wn * 32 + nt * 8 + ec;
#pragma unroll
                for (int h = 0; h < 2; ++h) {
                    float v0 = acc[mt][nt][2 * h], v1 = acc[mt][nt][2 * h + 1];
                    long long o = (r0 + 8 * h) * N + col;
                    *(uint32_t*)(Hb + o) = pack_hi(v0, v1);
                    *(uint32_t*)(Lb + o) = pack_lo(v0, v1);
                }
            }
        }
    }
}

// ---------------- row softmax: L fp32 -> A bf16 hi/lo, causal ---------------
__global__ void softmax_rows(const float* __restrict__ L, bf16* __restrict__ Ahi,
                             bf16* __restrict__ Alo, int Nn) {
    int b = blockIdx.y, i = blockIdx.x;
    const float* row = L + ((long long)b * Nn + i) * Nn;
    bf16* ah = Ahi + ((long long)b * Nn + i) * Nn;
    bf16* al = Alo + ((long long)b * Nn + i) * Nn;
    int nv = i + 1;
    int t = threadIdx.x;
    __shared__ float red[256];

    float m = -1e30f;
    for (int j = t; j < nv; j += 256) m = fmaxf(m, row[j]);
    red[t] = m; __syncthreads();
    for (int s = 128; s > 0; s >>= 1) {
        if (t < s) red[t] = fmaxf(red[t], red[t + s]);
        __syncthreads();
    }
    m = red[0]; __syncthreads();

    float ssum = 0.f;
    for (int j = t; j < nv; j += 256) ssum += __expf(row[j] - m);
    red[t] = ssum; __syncthreads();
    for (int s = 128; s > 0; s >>= 1) {
        if (t < s) red[t] += red[t + s];
        __syncthreads();
    }
    float inv = 1.f / red[0];

    for (int j = t; j < nv; j += 256) {
        float v = __expf(row[j] - m) * inv;
        bf16 h = __float2bfloat16(v);
        ah[j] = h;
        al[j] = __float2bfloat16(v - __bfloat162float(h));
    }
    bf16 zz = __float2bfloat16(0.f);
    for (int j = nv + t; j < Nn; j += 256) { ah[j] = zz; al[j] = zz; }
}

// ---------------- launch ----------------------------------------------------
static cudaStream_t make_stream() {
    cudaStream_t s;
    cudaStreamCreateWithFlags(&s, cudaStreamNonBlocking);
    return s;
}
static cudaEvent_t make_event() {
    cudaEvent_t e;
    cudaEventCreateWithFlags(&e, cudaEventDisableTiming);
    return e;
}

extern "C" void kernel_launch(void* const* d_in, const int* in_sizes, int n_in,
                              void* d_out, int out_size) {
    const float* X   = (const float*)d_in[0];
    const float* W_Q = (const float*)d_in[1];
    const float* W_K = (const float*)d_in[2];
    const float* W_V = (const float*)d_in[3];
    const float* W_O = (const float*)d_in[4];
    float* out = (float*)d_out;

    bf16 *Xhi, *Xlo, *XThi, *XTlo, *WQhi, *WQlo, *WKhi, *WKlo;
    bf16 *WOThi, *WOTlo, *WVThi, *WVTlo, *qhi, *qlo, *khi, *klo;
    bf16 *Mhi, *Mlo, *Ahi, *Alo, *cthi, *ctlo;
    float* L;
    cudaGetSymbolAddress((void**)&Xhi, g_Xhi);   cudaGetSymbolAddress((void**)&Xlo, g_Xlo);
    cudaGetSymbolAddress((void**)&XThi, g_XThi); cudaGetSymbolAddress((void**)&XTlo, g_XTlo);
    cudaGetSymbolAddress((void**)&WQhi, g_WQhi); cudaGetSymbolAddress((void**)&WQlo, g_WQlo);
    cudaGetSymbolAddress((void**)&WKhi, g_WKhi); cudaGetSymbolAddress((void**)&WKlo, g_WKlo);
    cudaGetSymbolAddress((void**)&WOThi, g_WOThi); cudaGetSymbolAddress((void**)&WOTlo, g_WOTlo);
    cudaGetSymbolAddress((void**)&WVThi, g_WVThi); cudaGetSymbolAddress((void**)&WVTlo, g_WVTlo);
    cudaGetSymbolAddress((void**)&qhi, g_qhi);   cudaGetSymbolAddress((void**)&qlo, g_qlo);
    cudaGetSymbolAddress((void**)&khi, g_khi);   cudaGetSymbolAddress((void**)&klo, g_klo);
    cudaGetSymbolAddress((void**)&Mhi, g_Mhi);   cudaGetSymbolAddress((void**)&Mlo, g_Mlo);
    cudaGetSymbolAddress((void**)&Ahi, g_Ahi);   cudaGetSymbolAddress((void**)&Alo, g_Alo);
    cudaGetSymbolAddress((void**)&cthi, g_cthi); cudaGetSymbolAddress((void**)&ctlo, g_ctlo);
    cudaGetSymbolAddress((void**)&L, g_L);

    cudaFuncSetAttribute(hgemm, cudaFuncAttributeMaxDynamicSharedMemorySize, GSMEM);

    static cudaStream_t s1 = make_stream();   // M' branch
    static cudaStream_t s2 = make_stream();   // k-projection branch
    static cudaEvent_t ev0 = make_event();    // conversions done
    static cudaEvent_t evK = make_event();    // k-projection done
    static cudaEvent_t evM = make_event();    // M' done

    const long long sX  = (long long)DDIM * NSEQ;
    const long long sXT = (long long)NSEQ * DDIM;
    const long long sQ  = (long long)NSEQ * KDIM;
    const long long sL  = (long long)NSEQ * NSEQ;

    dim3 tb(32, 8);
    // conversions (stream 0)
    convtrans_X<<<dim3(NSEQ / 32, DDIM / 32, BATCH), tb>>>(X, Xhi, Xlo, XThi, XTlo);
    convert_hl<<<(KDIM * DDIM / 4) / 256, 256>>>(W_Q, WQhi, WQlo, KDIM * DDIM);
    convert_hl<<<(KDIM * DDIM / 4) / 256, 256>>>(W_K, WKhi, WKlo, KDIM * DDIM);
    transpose_hl<<<dim3(DDIM / 32, KDIM / 32, 1), tb>>>(W_O, WOThi, WOTlo, KDIM, DDIM, 0, 0);
    transpose_hl<<<dim3(DDIM / 32, KDIM / 32, 1), tb>>>(W_V, WVThi, WVTlo, KDIM, DDIM, 0, 0);
    cudaEventRecord(ev0, 0);

    // branch M' on s1: M'[d][e] = sum_k WOT[d][k] * WVT[e][k]
    cudaStreamWaitEvent(s1, ev0, 0);
    hgemm<<<dim3(DDIM / TN, DDIM / TM, 1), 256, GSMEM, s1>>>(
        WOThi, WOTlo, WVThi, WVTlo, nullptr, Mhi, Mlo, nullptr,
        DDIM, DDIM, KDIM, 0, 0, 0, 0, 0, 0);
    cudaEventRecord(evM, s1);

    // branch k on s2: kk[j][k] = sum_d XT[j][d] * W_K[k][d]
    cudaStreamWaitEvent(s2, ev0, 0);
    hgemm<<<dim3(KDIM / TN, NSEQ / TM, BATCH), 256, GSMEM, s2>>>(
        XThi, XTlo, WKhi, WKlo, nullptr, khi, klo, nullptr,
        NSEQ, KDIM, DDIM, sXT, 0, sQ, 0, 0, 0);
    cudaEventRecord(evK, s2);

    // q on stream 0 (overlaps k and M')
    hgemm<<<dim3(KDIM / TN, NSEQ / TM, BATCH), 256, GSMEM>>>(
        XThi, XTlo, WQhi, WQlo, nullptr, qhi, qlo, nullptr,
        NSEQ, KDIM, DDIM, sXT, 0, sQ, 0, 0, 0);

    // join k, then logits: L[i][j] = sum_k q[i][k]*kk[j][k] (causal tile skip)
    cudaStreamWaitEvent(0, evK, 0);
    hgemm<<<dim3(NSEQ / TN, NSEQ / TM, BATCH), 256, GSMEM>>>(
        qhi, qlo, khi, klo, L, nullptr, nullptr, nullptr,
        NSEQ, NSEQ, KDIM, sQ, sQ, sL, 0, 1, 0);

    softmax_rows<<<dim3(NSEQ, BATCH), 256>>>(L, Ahi, Alo, NSEQ);

    // ctxT[i][e] = sum_t A[i][t] * X[e][t]  (k-loop capped at m0+TM)
    hgemm<<<dim3(DDIM / TN, NSEQ / TM, BATCH), 256, GSMEM>>>(
        Ahi, Alo, Xhi, Xlo, nullptr, cthi, ctlo, nullptr,
        NSEQ, DDIM, NSEQ, sL, sX, sXT, 0, 0, 1);

    // join M', then out[d][i] = X[d][i] + sum_e M'[d][e] * ctxT[i][e]
    cudaStreamWaitEvent(0, evM, 0);
    hgemm<<<dim3(NSEQ / TN, DDIM / TM, BATCH), 256, GSMEM>>>(
        Mhi, Mlo, cthi, ctlo, out, nullptr, nullptr, X,
        DDIM, NSEQ, DDIM, 0, sXT, sX, sX, 0, 0);
}

// round 9
// speedup vs baseline: 2.9996x; 1.0658x over previous
#include <cuda_runtime.h>
#include <cuda_bf16.h>
#include <cstdint>

#define BATCH 4
#define DDIM  1024
#define NSEQ  2048
#define KDIM  1024

typedef __nv_bfloat16 bf16;

// ---------------- scratch (device globals; zero-init bss) -------------------
__device__ bf16 g_Xhi [BATCH * DDIM * NSEQ], g_Xlo [BATCH * DDIM * NSEQ];   // (b,d,n)
__device__ bf16 g_XThi[BATCH * NSEQ * DDIM], g_XTlo[BATCH * NSEQ * DDIM];   // (b,i,d)
__device__ bf16 g_WQhi[KDIM * DDIM], g_WQlo[KDIM * DDIM];                   // (k,d)
__device__ bf16 g_WKhi[KDIM * DDIM], g_WKlo[KDIM * DDIM];
__device__ bf16 g_WOThi[DDIM * KDIM], g_WOTlo[DDIM * KDIM];                 // (d,k)
__device__ bf16 g_WVThi[DDIM * KDIM], g_WVTlo[DDIM * KDIM];                 // (e,k)
__device__ bf16 g_qhi [BATCH * NSEQ * KDIM], g_qlo [BATCH * NSEQ * KDIM];   // (b,i,k)
__device__ bf16 g_khi [BATCH * NSEQ * KDIM], g_klo [BATCH * NSEQ * KDIM];   // (b,j,k)
__device__ bf16 g_Mhi [DDIM * DDIM], g_Mlo [DDIM * DDIM];                   // (d,e)
__device__ float g_L  [BATCH * NSEQ * NSEQ];                                // logits fp32
__device__ bf16 g_Ahi [BATCH * NSEQ * NSEQ], g_Alo [BATCH * NSEQ * NSEQ];   // softmax out
__device__ bf16 g_cthi[BATCH * NSEQ * DDIM], g_ctlo[BATCH * NSEQ * DDIM];   // (b,i,e)

// ---------------- helpers ----------------------------------------------------
__device__ __forceinline__ uint32_t smem_u32(const void* p) {
    uint32_t a;
    asm("{ .reg .u64 t; cvta.to.shared.u64 t, %1; cvt.u32.u64 %0, t; }" : "=r"(a) : "l"(p));
    return a;
}
__device__ __forceinline__ void ldsm4(uint32_t* r, uint32_t addr) {
    asm volatile("ldmatrix.sync.aligned.m8n8.x4.shared.b16 {%0,%1,%2,%3}, [%4];"
                 : "=r"(r[0]), "=r"(r[1]), "=r"(r[2]), "=r"(r[3]) : "r"(addr));
}
__device__ __forceinline__ void mma16816(float* d, const uint32_t* a, const uint32_t* b) {
    asm volatile(
        "mma.sync.aligned.m16n8k16.row.col.f32.bf16.bf16.f32 "
        "{%0,%1,%2,%3}, {%4,%5,%6,%7}, {%8,%9}, {%0,%1,%2,%3};"
        : "+f"(d[0]), "+f"(d[1]), "+f"(d[2]), "+f"(d[3])
        : "r"(a[0]), "r"(a[1]), "r"(a[2]), "r"(a[3]), "r"(b[0]), "r"(b[1]));
}
__device__ __forceinline__ void cpasync16(uint32_t dst, const void* src) {
    asm volatile("cp.async.cg.shared.global [%0], [%1], 16;" :: "r"(dst), "l"(src));
}
__device__ __forceinline__ void cp_commit() { asm volatile("cp.async.commit_group;"); }
__device__ __forceinline__ void cp_wait1()  { asm volatile("cp.async.wait_group 1;"); }

__device__ __forceinline__ uint32_t pack_hi(float a, float b) {
    bf16 h0 = __float2bfloat16(a), h1 = __float2bfloat16(b);
    return (uint32_t)__bfloat16_as_ushort(h0) | ((uint32_t)__bfloat16_as_ushort(h1) << 16);
}
__device__ __forceinline__ uint32_t pack_lo(float a, float b) {
    bf16 h0 = __float2bfloat16(a), h1 = __float2bfloat16(b);
    float l0 = a - __bfloat162float(h0), l1 = b - __bfloat162float(h1);
    return (uint32_t)__bfloat16_as_ushort(__float2bfloat16(l0)) |
           ((uint32_t)__bfloat16_as_ushort(__float2bfloat16(l1)) << 16);
}

// ---------------- convert fp32 -> bf16 hi/lo --------------------------------
__global__ void convert_hl(const float* __restrict__ in, bf16* __restrict__ hi,
                           bf16* __restrict__ lo, long long n) {
    long long i = ((long long)blockIdx.x * blockDim.x + threadIdx.x) * 4;
    if (i >= n) return;
    float4 v = *(const float4*)(in + i);
    *(uint2*)(hi + i) = make_uint2(pack_hi(v.x, v.y), pack_hi(v.z, v.w));
    *(uint2*)(lo + i) = make_uint2(pack_lo(v.x, v.y), pack_lo(v.z, v.w));
}

// ---------------- transpose fp32 -> bf16 hi/lo: out[c][r] = in[r][c] --------
__global__ void transpose_hl(const float* __restrict__ in, bf16* __restrict__ hi,
                             bf16* __restrict__ lo, int rows, int cols,
                             long long sIn, long long sOut) {
    __shared__ float tile[32][33];
    const float* I = in + (long long)blockIdx.z * sIn;
    int r0 = blockIdx.y * 32, c0 = blockIdx.x * 32;
    int x = threadIdx.x, y = threadIdx.y;
#pragma unroll
    for (int j = y; j < 32; j += 8)
        tile[j][x] = I[(long long)(r0 + j) * cols + c0 + x];
    __syncthreads();
    long long zo = (long long)blockIdx.z * sOut;
#pragma unroll
    for (int j = y; j < 32; j += 8) {
        float v = tile[x][j];
        long long o = zo + (long long)(c0 + j) * rows + r0 + x;
        bf16 h = __float2bfloat16(v);
        hi[o] = h;
        lo[o] = __float2bfloat16(v - __bfloat162float(h));
    }
}

// ---------------- fused X: convert + transpose in one pass ------------------
__global__ void convtrans_X(const float* __restrict__ in,
                            bf16* __restrict__ hi, bf16* __restrict__ lo,
                            bf16* __restrict__ thi, bf16* __restrict__ tlo) {
    __shared__ float tile[32][33];
    long long zb = (long long)blockIdx.z * DDIM * NSEQ;
    int r0 = blockIdx.y * 32, c0 = blockIdx.x * 32;
    int x = threadIdx.x, y = threadIdx.y;
#pragma unroll
    for (int j = y; j < 32; j += 8) {
        long long o = zb + (long long)(r0 + j) * NSEQ + c0 + x;
        float v = in[o];
        tile[j][x] = v;
        bf16 h = __float2bfloat16(v);
        hi[o] = h;
        lo[o] = __float2bfloat16(v - __bfloat162float(h));
    }
    __syncthreads();
#pragma unroll
    for (int j = y; j < 32; j += 8) {
        float v = tile[x][j];
        long long o = zb + (long long)(c0 + j) * DDIM + r0 + x;
        bf16 h = __float2bfloat16(v);
        thi[o] = h;
        tlo[o] = __float2bfloat16(v - __bfloat162float(h));
    }
}

// ---------------- bf16 hi/lo HMMA NT GEMM -----------------------------------
#define TM 128
#define TN 128
#define KC 32
#define TILE_B 8192            // 128 rows x 64B (swizzled)
#define STAGE_B (4 * TILE_B)
#define STAGES 3
#define GSMEM (STAGES * STAGE_B)

__global__ void __launch_bounds__(256, 2)
hgemm(const bf16* __restrict__ Ahi_, const bf16* __restrict__ Alo_,
      const bf16* __restrict__ Bhi_, const bf16* __restrict__ Blo_,
      float* __restrict__ Cf, bf16* __restrict__ Chi, bf16* __restrict__ Clo,
      const float* __restrict__ Res,
      int M, int N, int Kk,
      long long sA, long long sB, long long sC, long long sRes,
      int causal, int kcap, int m_off, int n_off) {
    int by = (causal || kcap) ? (gridDim.y - 1 - blockIdx.y) : blockIdx.y;
    int m0 = m_off + by * TM;
    int n0 = n_off + blockIdx.x * TN;
    if (causal && n0 > m0 + TM - 1) return;

    extern __shared__ char sm[];
    uint32_t sb = smem_u32(sm);
    int tid = threadIdx.x, lane = tid & 31, wid = tid >> 5;
    int wm = wid & 1, wn = wid >> 1;
    long long z = blockIdx.z;

    int row = tid >> 1, seg0 = (tid & 1) * 2;
    int ssw = (row >> 1) & 3;
    uint32_t so0 = (uint32_t)(row * 64 + ((seg0 ^ ssw) << 4));
    uint32_t so1 = (uint32_t)(row * 64 + (((seg0 + 1) ^ ssw) << 4));
    const bf16* pAhi = Ahi_ + z * sA + (long long)(m0 + row) * Kk + seg0 * 8;
    const bf16* pAlo = Alo_ + z * sA + (long long)(m0 + row) * Kk + seg0 * 8;
    const bf16* pBhi = Bhi_ + z * sB + (long long)(n0 + row) * Kk + seg0 * 8;
    const bf16* pBlo = Blo_ + z * sB + (long long)(n0 + row) * Kk + seg0 * 8;

    int ra = wm * 64 + (lane & 15);
    int abit = lane >> 4;
    uint32_t aRow = (uint32_t)ra * 64;
    int swA = (ra >> 1) & 3;
    uint32_t colA[2] = { (uint32_t)(((0 + abit) ^ swA) << 4),
                         (uint32_t)(((2 + abit) ^ swA) << 4) };
    int rb = wn * 32 + ((lane >> 4) << 3) + (lane & 7);
    int bbit = (lane >> 3) & 1;
    uint32_t bRow = (uint32_t)rb * 64;
    int swB = (rb >> 1) & 3;
    uint32_t colB[2] = { (uint32_t)(((0 + bbit) ^ swB) << 4),
                         (uint32_t)(((2 + bbit) ^ swB) << 4) };

    float acc[4][4][4];
#pragma unroll
    for (int mt = 0; mt < 4; ++mt)
#pragma unroll
        for (int nt = 0; nt < 4; ++nt)
#pragma unroll
            for (int r = 0; r < 4; ++r) acc[mt][nt][r] = 0.f;

    int KkE = kcap ? (m0 + TM < Kk ? m0 + TM : Kk) : Kk;
    const int nc = KkE / KC;

#pragma unroll
    for (int s = 0; s < STAGES - 1; ++s) {
        long long off = (long long)s * KC;
        uint32_t d = sb + s * STAGE_B;
        cpasync16(d + 0 * TILE_B + so0, pAhi + off);
        cpasync16(d + 0 * TILE_B + so1, pAhi + off + 8);
        cpasync16(d + 1 * TILE_B + so0, pAlo + off);
        cpasync16(d + 1 * TILE_B + so1, pAlo + off + 8);
        cpasync16(d + 2 * TILE_B + so0, pBhi + off);
        cpasync16(d + 2 * TILE_B + so1, pBhi + off + 8);
        cpasync16(d + 3 * TILE_B + so0, pBlo + off);
        cpasync16(d + 3 * TILE_B + so1, pBlo + off + 8);
        cp_commit();
    }

    for (int c = 0; c < nc; ++c) {
        cp_wait1();
        __syncthreads();
        if (c + 2 < nc) {
            int st = (c + 2) % STAGES;
            long long off = (long long)(c + 2) * KC;
            uint32_t d = sb + st * STAGE_B;
            cpasync16(d + 0 * TILE_B + so0, pAhi + off);
            cpasync16(d + 0 * TILE_B + so1, pAhi + off + 8);
            cpasync16(d + 1 * TILE_B + so0, pAlo + off);
            cpasync16(d + 1 * TILE_B + so1, pAlo + off + 8);
            cpasync16(d + 2 * TILE_B + so0, pBhi + off);
            cpasync16(d + 2 * TILE_B + so1, pBhi + off + 8);
            cpasync16(d + 3 * TILE_B + so0, pBlo + off);
            cpasync16(d + 3 * TILE_B + so1, pBlo + off + 8);
            cp_commit();
        } else {
            cp_commit();
        }

        uint32_t bA = sb + (c % STAGES) * STAGE_B;
        uint32_t bAhi = bA, bAlo = bA + TILE_B, bBhi = bA + 2 * TILE_B, bBlo = bA + 3 * TILE_B;

#pragma unroll
        for (int kk2 = 0; kk2 < 2; ++kk2) {
            uint32_t ah[4][4], bh[4][2], bl[4][2];
#pragma unroll
            for (int mt = 0; mt < 4; ++mt)
                ldsm4(ah[mt], bAhi + aRow + mt * 1024 + colA[kk2]);
#pragma unroll
            for (int jp = 0; jp < 2; ++jp) {
                uint32_t r[4];
                ldsm4(r, bBhi + bRow + jp * 1024 + colB[kk2]);
                bh[2 * jp][0] = r[0]; bh[2 * jp][1] = r[1];
                bh[2 * jp + 1][0] = r[2]; bh[2 * jp + 1][1] = r[3];
            }
#pragma unroll
            for (int jp = 0; jp < 2; ++jp) {
                uint32_t r[4];
                ldsm4(r, bBlo + bRow + jp * 1024 + colB[kk2]);
                bl[2 * jp][0] = r[0]; bl[2 * jp][1] = r[1];
                bl[2 * jp + 1][0] = r[2]; bl[2 * jp + 1][1] = r[3];
            }
#pragma unroll
            for (int mt = 0; mt < 4; ++mt)
#pragma unroll
                for (int nt = 0; nt < 4; ++nt)
                    mma16816(acc[mt][nt], ah[mt], bh[nt]);

            uint32_t al[4][4];
#pragma unroll
            for (int mt = 0; mt < 4; ++mt)
                ldsm4(al[mt], bAlo + aRow + mt * 1024 + colA[kk2]);
#pragma unroll
            for (int mt = 0; mt < 4; ++mt)
#pragma unroll
                for (int nt = 0; nt < 4; ++nt)
                    mma16816(acc[mt][nt], ah[mt], bl[nt]);
#pragma unroll
            for (int mt = 0; mt < 4; ++mt)
#pragma unroll
                for (int nt = 0; nt < 4; ++nt)
                    mma16816(acc[mt][nt], al[mt], bh[nt]);
        }
    }

    int er = lane >> 2, ec = (lane & 3) * 2;
    if (Cf) {
        float* Cb = Cf + z * sC;
        const float* Rb = Res ? Res + z * sRes : nullptr;
#pragma unroll
        for (int mt = 0; mt < 4; ++mt) {
#pragma unroll
            for (int nt = 0; nt < 4; ++nt) {
                long long r0 = (long long)(m0 + wm * 64 + mt * 16 + er);
                int col = n0 + wn * 32 + nt * 8 + ec;
                float2 v0 = make_float2(acc[mt][nt][0], acc[mt][nt][1]);
                float2 v1 = make_float2(acc[mt][nt][2], acc[mt][nt][3]);
                if (Rb) {
                    float2 q0 = *(const float2*)(Rb + r0 * N + col);
                    float2 q1 = *(const float2*)(Rb + (r0 + 8) * N + col);
                    v0.x += q0.x; v0.y += q0.y; v1.x += q1.x; v1.y += q1.y;
                }
                *(float2*)(Cb + r0 * N + col)       = v0;
                *(float2*)(Cb + (r0 + 8) * N + col) = v1;
            }
        }
    } else {
        bf16* Hb = Chi + z * sC;
        bf16* Lb = Clo + z * sC;
#pragma unroll
        for (int mt = 0; mt < 4; ++mt) {
#pragma unroll
            for (int nt = 0; nt < 4; ++nt) {
                long long r0 = (long long)(m0 + wm * 64 + mt * 16 + er);
                int col = n0 + wn * 32 + nt * 8 + ec;
#pragma unroll
                for (int h = 0; h < 2; ++h) {
                    float v0 = acc[mt][nt][2 * h], v1 = acc[mt][nt][2 * h + 1];
                    long long o = (r0 + 8 * h) * N + col;
                    *(uint32_t*)(Hb + o) = pack_hi(v0, v1);
                    *(uint32_t*)(Lb + o) = pack_lo(v0, v1);
                }
            }
        }
    }
}

// ---------------- row softmax: L fp32 -> A bf16 hi/lo, causal ---------------
__global__ void softmax_rows(const float* __restrict__ L, bf16* __restrict__ Ahi,
                             bf16* __restrict__ Alo, int Nn, int i_off) {
    int b = blockIdx.y, i = i_off + blockIdx.x;
    const float* row = L + ((long long)b * Nn + i) * Nn;
    bf16* ah = Ahi + ((long long)b * Nn + i) * Nn;
    bf16* al = Alo + ((long long)b * Nn + i) * Nn;
    int nv = i + 1;
    int t = threadIdx.x;
    __shared__ float red[256];

    float m = -1e30f;
    for (int j = t; j < nv; j += 256) m = fmaxf(m, row[j]);
    red[t] = m; __syncthreads();
    for (int s = 128; s > 0; s >>= 1) {
        if (t < s) red[t] = fmaxf(red[t], red[t + s]);
        __syncthreads();
    }
    m = red[0]; __syncthreads();

    float ssum = 0.f;
    for (int j = t; j < nv; j += 256) ssum += __expf(row[j] - m);
    red[t] = ssum; __syncthreads();
    for (int s = 128; s > 0; s >>= 1) {
        if (t < s) red[t] += red[t + s];
        __syncthreads();
    }
    float inv = 1.f / red[0];

    for (int j = t; j < nv; j += 256) {
        float v = __expf(row[j] - m) * inv;
        bf16 h = __float2bfloat16(v);
        ah[j] = h;
        al[j] = __float2bfloat16(v - __bfloat162float(h));
    }
    bf16 zz = __float2bfloat16(0.f);
    for (int j = nv + t; j < Nn; j += 256) { ah[j] = zz; al[j] = zz; }
}

// ---------------- launch ----------------------------------------------------
static cudaStream_t make_stream() {
    cudaStream_t s;
    cudaStreamCreateWithFlags(&s, cudaStreamNonBlocking);
    return s;
}
static cudaEvent_t make_event() {
    cudaEvent_t e;
    cudaEventCreateWithFlags(&e, cudaEventDisableTiming);
    return e;
}

extern "C" void kernel_launch(void* const* d_in, const int* in_sizes, int n_in,
                              void* d_out, int out_size) {
    const float* X   = (const float*)d_in[0];
    const float* W_Q = (const float*)d_in[1];
    const float* W_K = (const float*)d_in[2];
    const float* W_V = (const float*)d_in[3];
    const float* W_O = (const float*)d_in[4];
    float* out = (float*)d_out;

    bf16 *Xhi, *Xlo, *XThi, *XTlo, *WQhi, *WQlo, *WKhi, *WKlo;
    bf16 *WOThi, *WOTlo, *WVThi, *WVTlo, *qhi, *qlo, *khi, *klo;
    bf16 *Mhi, *Mlo, *Ahi, *Alo, *cthi, *ctlo;
    float* L;
    cudaGetSymbolAddress((void**)&Xhi, g_Xhi);   cudaGetSymbolAddress((void**)&Xlo, g_Xlo);
    cudaGetSymbolAddress((void**)&XThi, g_XThi); cudaGetSymbolAddress((void**)&XTlo, g_XTlo);
    cudaGetSymbolAddress((void**)&WQhi, g_WQhi); cudaGetSymbolAddress((void**)&WQlo, g_WQlo);
    cudaGetSymbolAddress((void**)&WKhi, g_WKhi); cudaGetSymbolAddress((void**)&WKlo, g_WKlo);
    cudaGetSymbolAddress((void**)&WOThi, g_WOThi); cudaGetSymbolAddress((void**)&WOTlo, g_WOTlo);
    cudaGetSymbolAddress((void**)&WVThi, g_WVThi); cudaGetSymbolAddress((void**)&WVTlo, g_WVTlo);
    cudaGetSymbolAddress((void**)&qhi, g_qhi);   cudaGetSymbolAddress((void**)&qlo, g_qlo);
    cudaGetSymbolAddress((void**)&khi, g_khi);   cudaGetSymbolAddress((void**)&klo, g_klo);
    cudaGetSymbolAddress((void**)&Mhi, g_Mhi);   cudaGetSymbolAddress((void**)&Mlo, g_Mlo);
    cudaGetSymbolAddress((void**)&Ahi, g_Ahi);   cudaGetSymbolAddress((void**)&Alo, g_Alo);
    cudaGetSymbolAddress((void**)&cthi, g_cthi); cudaGetSymbolAddress((void**)&ctlo, g_ctlo);
    cudaGetSymbolAddress((void**)&L, g_L);

    cudaFuncSetAttribute(hgemm, cudaFuncAttributeMaxDynamicSharedMemorySize, GSMEM);

    static cudaStream_t s1 = make_stream();
    static cudaStream_t s2 = make_stream();
    static cudaEvent_t ev0  = make_event();
    static cudaEvent_t evK  = make_event();
    static cudaEvent_t evLH = make_event();   // logits-H done
    static cudaEvent_t evM  = make_event();
    static cudaEvent_t evOH = make_event();   // out-H done

    const long long sX  = (long long)DDIM * NSEQ;
    const long long sXT = (long long)NSEQ * DDIM;
    const long long sQ  = (long long)NSEQ * KDIM;
    const long long sL  = (long long)NSEQ * NSEQ;
    const int HALF = NSEQ / 2;                 // 1024

    dim3 tb(32, 8);
    // conversions (stream 0)
    convtrans_X<<<dim3(NSEQ / 32, DDIM / 32, BATCH), tb>>>(X, Xhi, Xlo, XThi, XTlo);
    convert_hl<<<(KDIM * DDIM / 4) / 256, 256>>>(W_Q, WQhi, WQlo, KDIM * DDIM);
    convert_hl<<<(KDIM * DDIM / 4) / 256, 256>>>(W_K, WKhi, WKlo, KDIM * DDIM);
    transpose_hl<<<dim3(DDIM / 32, KDIM / 32, 1), tb>>>(W_O, WOThi, WOTlo, KDIM, DDIM, 0, 0);
    transpose_hl<<<dim3(DDIM / 32, KDIM / 32, 1), tb>>>(W_V, WVThi, WVTlo, KDIM, DDIM, 0, 0);
    cudaEventRecord(ev0, 0);

    // M' on s1 (overlaps q/k): M'[d][e] = sum_k WOT[d][k] WVT[e][k]
    cudaStreamWaitEvent(s1, ev0, 0);
    hgemm<<<dim3(DDIM / TN, DDIM / TM, 1), 256, GSMEM, s1>>>(
        WOThi, WOTlo, WVThi, WVTlo, nullptr, Mhi, Mlo, nullptr,
        DDIM, DDIM, KDIM, 0, 0, 0, 0, 0, 0, 0, 0);
    cudaEventRecord(evM, s1);

    // k on s2 (packs with q)
    cudaStreamWaitEvent(s2, ev0, 0);
    hgemm<<<dim3(KDIM / TN, NSEQ / TM, BATCH), 256, GSMEM, s2>>>(
        XThi, XTlo, WKhi, WKlo, nullptr, khi, klo, nullptr,
        NSEQ, KDIM, DDIM, sXT, 0, sQ, 0, 0, 0, 0, 0);
    cudaEventRecord(evK, s2);

    // q on stream 0
    hgemm<<<dim3(KDIM / TN, NSEQ / TM, BATCH), 256, GSMEM>>>(
        XThi, XTlo, WQhi, WQlo, nullptr, qhi, qlo, nullptr,
        NSEQ, KDIM, DDIM, sXT, 0, sQ, 0, 0, 0, 0, 0);

    cudaStreamWaitEvent(0, evK, 0);

    // ---- pipelined middle: H half (i >= 1024) feeds s1, L half stays on 0 --
    // logits-H: rows [1024,2048)
    hgemm<<<dim3(NSEQ / TN, HALF / TM, BATCH), 256, GSMEM>>>(
        qhi, qlo, khi, klo, L, nullptr, nullptr, nullptr,
        NSEQ, NSEQ, KDIM, sQ, sQ, sL, 0, 1, 0, HALF, 0);
    cudaEventRecord(evLH, 0);

    // logits-L: rows [0,1024)
    hgemm<<<dim3(NSEQ / TN, HALF / TM, BATCH), 256, GSMEM>>>(
        qhi, qlo, khi, klo, L, nullptr, nullptr, nullptr,
        NSEQ, NSEQ, KDIM, sQ, sQ, sL, 0, 1, 0, 0, 0);

    // s1 branch: softmax-H -> ctx-H -> out-H
    cudaStreamWaitEvent(s1, evLH, 0);
    softmax_rows<<<dim3(HALF, BATCH), 256, 0, s1>>>(L, Ahi, Alo, NSEQ, HALF);
    hgemm<<<dim3(DDIM / TN, HALF / TM, BATCH), 256, GSMEM, s1>>>(
        Ahi, Alo, Xhi, Xlo, nullptr, cthi, ctlo, nullptr,
        NSEQ, DDIM, NSEQ, sL, sX, sXT, 0, 0, 1, HALF, 0);
    // out-H: columns i in [1024,2048): out[d][i] = X[d][i] + sum_e M'[d][e] ctxT[i][e]
    hgemm<<<dim3(HALF / TN, DDIM / TM, BATCH), 256, GSMEM, s1>>>(
        Mhi, Mlo, cthi, ctlo, out, nullptr, nullptr, X,
        DDIM, NSEQ, DDIM, 0, sXT, sX, sX, 0, 0, 0, HALF);
    cudaEventRecord(evOH, s1);

    // stream 0: softmax-L -> ctx-L -> out-L
    softmax_rows<<<dim3(HALF, BATCH), 256>>>(L, Ahi, Alo, NSEQ, 0);
    hgemm<<<dim3(DDIM / TN, HALF / TM, BATCH), 256, GSMEM>>>(
        Ahi, Alo, Xhi, Xlo, nullptr, cthi, ctlo, nullptr,
        NSEQ, DDIM, NSEQ, sL, sX, sXT, 0, 0, 1, 0, 0);
    cudaStreamWaitEvent(0, evM, 0);
    hgemm<<<dim3(HALF / TN, DDIM / TM, BATCH), 256, GSMEM>>>(
        Mhi, Mlo, cthi, ctlo, out, nullptr, nullptr, X,
        DDIM, NSEQ, DDIM, 0, sXT, sX, sX, 0, 0, 0, 0);

    // join H branch before returning
    cudaStreamWaitEvent(0, evOH, 0);
}